// round 11
// baseline (speedup 1.0000x reference)
#include <cuda_runtime.h>
#include <math.h>

#define BATCH 512
#define TT    2048
#define INP   32
#define H     256
#define DTC   0.1f
#define EPSC  1e-5f
#define BB    8
#define GRID  (BATCH / BB)   /* 64 blocks */
#define NT    512            /* 2 layer-groups x 256 */

typedef unsigned long long ull;

// Transposed-interleaved weight scratch: layout [k/4][j][k&3] per matrix.
#define WOFF_A0 0
#define WOFF_A1 (1 * H * H)
#define WOFF_R0 (2 * H * H)
#define WOFF_R1 (3 * H * H)
#define WOFF_I1 (4 * H * H)
#define WOFF_SK (5 * H * H)
#define WOFF_I0 (6 * H * H)
__device__ __align__(16) float g_Wt[6 * H * H + INP * H];

// Dynamic smem layout (bytes). A = rows 0-3, B = rows 4-7.
#define SM_H0A   0        /* 2 x 4096 ping-pong */
#define SM_H0B   8192     /* 2 x 4096 */
#define SM_H1A   16384    /* 2 x 4096 */
#define SM_H1B   24576    /* 2 x 4096 */
#define SM_HA0A  32768    /* 4096 */
#define SM_HA0B  36864    /* 4096 */
#define SM_HA1A  40960    /* 4096 */
#define SM_HA1B  45056    /* 4096 */
#define SM_SKPA  49152    /* 4096 */
#define SM_SKPB  53248    /* 4096 */
#define SM_XQA   57344    /* 512 */
#define SM_XQB   57856    /* 512 */
#define SM_RED0  58368    /* 512 */
#define SM_RED1  58880    /* 512 */
#define SM_STAT0 59392    /* 64 */
#define SM_STAT1 59456    /* 64 */
#define SM_EW1   59520    /* 32 */
#define SMEM_BYTES 59648

__device__ __forceinline__ float sigmoidf_(float v) {
    return 1.0f / (1.0f + expf(-v));
}
__device__ __forceinline__ void ffma2(ull& d, ull a, ull b) {
    asm("fma.rn.f32x2 %0, %1, %2, %0;" : "+l"(d) : "l"(a), "l"(b));
}
__device__ __forceinline__ ull fadd2(ull a, ull b) {
    ull r; asm("add.rn.f32x2 %0, %1, %2;" : "=l"(r) : "l"(a), "l"(b)); return r;
}
__device__ __forceinline__ float hadd2(ull a) {
    float lo, hi; asm("mov.b64 {%0, %1}, %2;" : "=f"(lo), "=f"(hi) : "l"(a));
    return lo + hi;
}
__device__ __forceinline__ void barx(int id) {
    asm volatile("bar.sync %0, %1;" :: "r"(id), "r"(256) : "memory");
}

// Group-local reduction over 8 warps of NV values -> stat[0..NV-1].
template <int NV>
__device__ __forceinline__ void group_reduce(float* vals, int barid, int gt,
                                             float (*red)[16], float* stat) {
    #pragma unroll
    for (int o = 16; o > 0; o >>= 1) {
        #pragma unroll
        for (int i = 0; i < NV; i++)
            vals[i] += __shfl_xor_sync(0xffffffffu, vals[i], o);
    }
    int w = gt >> 5, l = gt & 31;
    if (l == 0) {
        #pragma unroll
        for (int i = 0; i < NV; i++) red[w][i] = vals[i];
    }
    barx(barid);
    if (gt < NV) {
        float a = 0.f;
        #pragma unroll
        for (int w2 = 0; w2 < 8; w2++) a += red[w2][gt];
        stat[gt] = a;
    }
    barx(barid);
}

// Write unit-j row values v[0..3] into pair-interleaved layout:
// buf[p*8 + {0..3}] = (h_2p[r0], h_2p+1[r0], h_2p[r1], h_2p+1[r1]); +4 = r2,r3.
__device__ __forceinline__ void writePair(float* buf, int j, const float* v) {
    float o0 = __shfl_xor_sync(0xffffffffu, v[0], 1);
    float o1 = __shfl_xor_sync(0xffffffffu, v[1], 1);
    float o2 = __shfl_xor_sync(0xffffffffu, v[2], 1);
    float o3 = __shfl_xor_sync(0xffffffffu, v[3], 1);
    int p = j >> 1;
    if ((j & 1) == 0) *(float4*)(buf + p * 8)     = make_float4(v[0], o0, v[1], o1);
    else              *(float4*)(buf + p * 8 + 4) = make_float4(o2, v[2], o3, v[3]);
}

// Dual-column GEMM over NCH 4-k chunks, shared weights across TWO row-quads.
// Weights: packed (w_k,w_k+1) pairs, coalesced LDG.128, prefetch distance 1.
// h: pair-layout smem (quad A rows 0-3, quad B rows 4-7).
// xA/yA: colX/colY accs rows0-3; xB/yB: rows4-7. Summation order per row
// identical to the BB=4 version (bit-exact numerics per batch row).
template <int NCH>
__device__ __forceinline__ void gemm2x(const ulonglong2* __restrict__ wX,
                                       const ulonglong2* __restrict__ wY,
                                       const ulonglong2* __restrict__ hA,
                                       const ulonglong2* __restrict__ hB,
                                       ull* xA, ull* xB, ull* yA, ull* yB) {
    ulonglong2 wx = __ldg(wX), wy = __ldg(wY);
    #pragma unroll 2
    for (int i = 0; i < NCH; i++) {
        ulonglong2 cwx = wx, cwy = wy;
        if (i + 1 < NCH) {
            wx = __ldg(wX + (i + 1) * 256);
            wy = __ldg(wY + (i + 1) * 256);
        }
        ulonglong2 a0 = hA[4 * i],     a1 = hA[4 * i + 1];
        ulonglong2 a2 = hA[4 * i + 2], a3 = hA[4 * i + 3];
        ulonglong2 b0 = hB[4 * i],     b1 = hB[4 * i + 1];
        ulonglong2 b2 = hB[4 * i + 2], b3 = hB[4 * i + 3];
        ffma2(xA[0], a0.x, cwx.x); ffma2(xA[1], a0.y, cwx.x);
        ffma2(xA[2], a1.x, cwx.x); ffma2(xA[3], a1.y, cwx.x);
        ffma2(xA[0], a2.x, cwx.y); ffma2(xA[1], a2.y, cwx.y);
        ffma2(xA[2], a3.x, cwx.y); ffma2(xA[3], a3.y, cwx.y);
        ffma2(xB[0], b0.x, cwx.x); ffma2(xB[1], b0.y, cwx.x);
        ffma2(xB[2], b1.x, cwx.x); ffma2(xB[3], b1.y, cwx.x);
        ffma2(xB[0], b2.x, cwx.y); ffma2(xB[1], b2.y, cwx.y);
        ffma2(xB[2], b3.x, cwx.y); ffma2(xB[3], b3.y, cwx.y);
        ffma2(yA[0], a0.x, cwy.x); ffma2(yA[1], a0.y, cwy.x);
        ffma2(yA[2], a1.x, cwy.x); ffma2(yA[3], a1.y, cwy.x);
        ffma2(yA[0], a2.x, cwy.y); ffma2(yA[1], a2.y, cwy.y);
        ffma2(yA[2], a3.x, cwy.y); ffma2(yA[3], a3.y, cwy.y);
        ffma2(yB[0], b0.x, cwy.x); ffma2(yB[1], b0.y, cwy.x);
        ffma2(yB[2], b1.x, cwy.x); ffma2(yB[3], b1.y, cwy.x);
        ffma2(yB[0], b2.x, cwy.y); ffma2(yB[1], b2.y, cwy.y);
        ffma2(yB[2], b3.x, cwy.y); ffma2(yB[3], b3.y, cwy.y);
    }
}

// Single-column GEMM, shared weights across two row-quads (for in0, full k).
template <int NCH>
__device__ __forceinline__ void gemm1x(const ulonglong2* __restrict__ wp,
                                       const ulonglong2* __restrict__ hA,
                                       const ulonglong2* __restrict__ hB,
                                       ull* accA, ull* accB) {
    ulonglong2 n = __ldg(wp);
    #pragma unroll
    for (int i = 0; i < NCH; i++) {
        ulonglong2 w = n;
        if (i + 1 < NCH) n = __ldg(wp + (i + 1) * 256);
        ulonglong2 a0 = hA[4 * i],     a1 = hA[4 * i + 1];
        ulonglong2 a2 = hA[4 * i + 2], a3 = hA[4 * i + 3];
        ulonglong2 b0 = hB[4 * i],     b1 = hB[4 * i + 1];
        ulonglong2 b2 = hB[4 * i + 2], b3 = hB[4 * i + 3];
        ffma2(accA[0], a0.x, w.x); ffma2(accA[1], a0.y, w.x);
        ffma2(accA[2], a1.x, w.x); ffma2(accA[3], a1.y, w.x);
        ffma2(accA[0], a2.x, w.y); ffma2(accA[1], a2.y, w.y);
        ffma2(accA[2], a3.x, w.y); ffma2(accA[3], a3.y, w.y);
        ffma2(accB[0], b0.x, w.x); ffma2(accB[1], b0.y, w.x);
        ffma2(accB[2], b1.x, w.x); ffma2(accB[3], b1.y, w.x);
        ffma2(accB[0], b2.x, w.y); ffma2(accB[1], b2.y, w.y);
        ffma2(accB[2], b3.x, w.y); ffma2(accB[3], b3.y, w.y);
    }
}

// Exchange colY partials with same-warp partner (lane j^16) and finish col-j
// sums for one row-quad. No barrier, no smem: pure warp shuffle.
__device__ __forceinline__ void combineShfl(const ull* aX, const ull* aY, float* res) {
    #pragma unroll
    for (int r = 0; r < 4; r++) {
        ull p = __shfl_xor_sync(0xffffffffu, aY[r], 16);
        res[r] = hadd2(fadd2(aX[r], p));
    }
}

// ---------------------------------------------------------------------------
// Kernel 0: transpose weights into [k/4][j][k&3] interleaved layout.
// ---------------------------------------------------------------------------
__global__ void transpose_kernel(
    const float* __restrict__ A0, const float* __restrict__ A1,
    const float* __restrict__ R0, const float* __restrict__ R1,
    const float* __restrict__ I1, const float* __restrict__ SK,
    const float* __restrict__ I0)
{
    int idx = blockIdx.x * blockDim.x + threadIdx.x;
    const int BIG = 6 * H * H;
    if (idx < BIG) {
        int m = idx >> 16, rem = idx & 65535;
        int k = rem >> 8, j = rem & 255;
        const float* src = (m == 0) ? A0 : (m == 1) ? A1 : (m == 2) ? R0
                         : (m == 3) ? R1 : (m == 4) ? I1 : SK;
        g_Wt[(m << 16) + (k >> 2) * (H * 4) + j * 4 + (k & 3)] = src[rem];
    } else if (idx < BIG + INP * H) {
        int rem = idx - BIG;
        int k = rem >> 8, j = rem & 255;
        g_Wt[BIG + (k >> 2) * (H * 4) + j * 4 + (k & 3)] = I0[rem];
    }
}

// ---------------------------------------------------------------------------
// Kernel 1: ew0[b,t] = mask * sigmoid([x_t, x_{t-1}] @ Wev0 + bev0)
// ---------------------------------------------------------------------------
__global__ void ew0_kernel(const float* __restrict__ x,
                           const float* __restrict__ Wev0,
                           const float* __restrict__ bev0,
                           float* __restrict__ ew0_out) {
    int idx = blockIdx.x * blockDim.x + threadIdx.x;
    if (idx >= BATCH * TT) return;
    int t = idx & (TT - 1);
    float r = 0.f;
    if (t > 0) {
        const float* xc = x + (size_t)idx * INP;
        const float* xp = xc - INP;
        float s = bev0[0];
        #pragma unroll
        for (int i = 0; i < INP; i++) s += xc[i] * Wev0[i];
        #pragma unroll
        for (int i = 0; i < INP; i++) s += xp[i] * Wev0[INP + i];
        r = sigmoidf_(s);
    }
    ew0_out[idx] = r;
}

// ---------------------------------------------------------------------------
// Kernel 2: persistent recurrence. 8 batch rows/block (two quads sharing
// every weight fetch -> half the L2 weight traffic of BB=4).
// 512 threads = 2 layer-groups x 256 units. Thread j computes cols {j, j^16}
// over k-half ((j>>4)&1); partner in-warp; combine via shfl.
// ---------------------------------------------------------------------------
__global__ __launch_bounds__(NT, 1) void liquid_kernel(
    const float* __restrict__ x,
    const float* __restrict__ bin0,  const float* __restrict__ brec0,
    const float* __restrict__ battn0,
    const float* __restrict__ tau0,  const float* __restrict__ gamma0, const float* __restrict__ beta0,
    const float* __restrict__ bin1,  const float* __restrict__ brec1,
    const float* __restrict__ battn1,
    const float* __restrict__ Wev1,  const float* __restrict__ bev1,
    const float* __restrict__ tau1,  const float* __restrict__ gamma1, const float* __restrict__ beta1,
    const float* __restrict__ bskip,
    const float* __restrict__ Wout,  const float* __restrict__ bout,
    float* __restrict__ out,
    const float* __restrict__ ew0_all,
    float* __restrict__ ew1_all)
{
    extern __shared__ __align__(16) char smraw[];

    const int tid  = threadIdx.x;
    const int g    = tid >> 8;        // layer-group
    const int j    = tid & 255;       // unit / group-local tid
    const int s    = (j >> 4) & 1;    // k-half (partner j^16 in same warp)
    const int row0 = blockIdx.x * BB;
    const int barid = 1 + g;

    float* ha0A = (float*)(smraw + SM_HA0A);
    float* ha0B = (float*)(smraw + SM_HA0B);
    float* ha1A = (float*)(smraw + SM_HA1A);
    float* ha1B = (float*)(smraw + SM_HA1B);
    float* skpA = (float*)(smraw + SM_SKPA);
    float* skpB = (float*)(smraw + SM_SKPB);
    float* xqA  = (float*)(smraw + SM_XQA);
    float* xqB  = (float*)(smraw + SM_XQB);
    float (*red)[16] = (float (*)[16])(smraw + (g ? SM_RED1 : SM_RED0));
    float* stat      = (float*)(smraw + (g ? SM_STAT1 : SM_STAT0));
    float* ew1_s     = (float*)(smraw + SM_EW1);

    // ---- per-group constants ----
    float c_battn, c_brec, it, c_g, c_b;
    float c_bin0 = 0.f, c_bin1 = 0.f, wv1a = 0.f, wv1b = 0.f, c_bev1 = 0.f;
    float c_bskip = 0.f, c_wout = 0.f;
    if (g == 0) {
        c_battn = battn0[j]; c_brec = brec0[j];
        it = DTC / fminf(fmaxf(tau0[j], 0.1f), 10.0f);
        c_g = gamma0[j]; c_b = beta0[j];
        c_bin0 = bin0[j]; c_bskip = bskip[j];
        wv1a = Wev1[j]; wv1b = Wev1[H + j]; c_bev1 = bev1[0];
    } else {
        c_battn = battn1[j]; c_brec = brec1[j];
        it = DTC / fminf(fmaxf(tau1[j], 0.1f), 10.0f);
        c_g = gamma1[j]; c_b = beta1[j];
        c_bin1 = bin1[j]; c_wout = Wout[j];
    }
    const float gw = c_g * wv1a;

    float C2 = 0.f, C3 = 0.f;
    if (g == 0) {
        float cc[2] = { gw, c_b * wv1a };
        group_reduce<2>(cc, barid, j, red, stat);
        C2 = stat[0]; C3 = stat[1];
    }

    // Weight bases: matrix base + k-half offset (ulonglong2 units).
    const int so = s * 32 * 256;
    const ulonglong2* WB = (const ulonglong2*)(g_Wt + (g ? WOFF_A1 : WOFF_A0)) + so;
    const ulonglong2* WC = (const ulonglong2*)(g_Wt + (g ? WOFF_R1 : WOFF_R0)) + so;
    const ulonglong2* WE = (const ulonglong2*)(g_Wt + (g ? WOFF_I1 : WOFF_SK)) + so;
    const ulonglong2* WI = (const ulonglong2*)(g_Wt + WOFF_I0) + j;
    const int jx = j ^ 16;

    float hown[BB] = {0.f, 0.f, 0.f, 0.f, 0.f, 0.f, 0.f, 0.f};
    if (g == 0) {
        *(float4*)((float*)(smraw + SM_H0A) + j * 4) = make_float4(0.f, 0.f, 0.f, 0.f);
        *(float4*)((float*)(smraw + SM_H0B) + j * 4) = make_float4(0.f, 0.f, 0.f, 0.f);
    } else {
        *(float4*)((float*)(smraw + SM_H1A) + j * 4) = make_float4(0.f, 0.f, 0.f, 0.f);
        *(float4*)((float*)(smraw + SM_H1B) + j * 4) = make_float4(0.f, 0.f, 0.f, 0.f);
    }
    __syncthreads();

    for (int t = 0; t < TT; t++) {
        const int co = (t & 1) * 4096, no = co ^ 4096;
        float* h0curA = (float*)(smraw + SM_H0A + co);
        float* h0curB = (float*)(smraw + SM_H0B + co);
        float* h1curA = (float*)(smraw + SM_H1A + co);
        float* h1curB = (float*)(smraw + SM_H1B + co);
        float* h0nxtA = (float*)(smraw + SM_H0A + no);
        float* h0nxtB = (float*)(smraw + SM_H0B + no);
        float* h1nxtA = (float*)(smraw + SM_H1A + no);
        float* h1nxtB = (float*)(smraw + SM_H1B + no);

        if (g == 0) {
            // ---- A: ew0 + x_t staging ----
            float e0r[BB];
            #pragma unroll
            for (int r = 0; r < BB; r++)
                e0r[r] = ew0_all[(size_t)(row0 + r) * TT + t];
            if (j < INP) {
                float xv[4], xw[4];
                #pragma unroll
                for (int r = 0; r < 4; r++)
                    xv[r] = x[((size_t)(row0 + r) * TT + t) * INP + j];
                #pragma unroll
                for (int r = 0; r < 4; r++)
                    xw[r] = x[((size_t)(row0 + 4 + r) * TT + t) * INP + j];
                writePair(xqA, j, xv);
                writePair(xqB, j, xw);
            }
            barx(1);

            // ---- B: attn0 (dual-col, two quads) + in0 ----
            float avLo[4], avHi[4];
            {
                ull xA[4] = {0,0,0,0}, xB[4] = {0,0,0,0};
                ull yA[4] = {0,0,0,0}, yB[4] = {0,0,0,0};
                gemm2x<32>(WB + j, WB + jx,
                           (const ulonglong2*)h0curA + s * 128,
                           (const ulonglong2*)h0curB + s * 128,
                           xA, xB, yA, yB);
                combineShfl(xA, yA, avLo);
                combineShfl(xB, yB, avHi);
            }
            float i0t[BB];
            {
                ull iaA[4] = {0,0,0,0}, iaB[4] = {0,0,0,0};
                gemm1x<8>(WI, (const ulonglong2*)xqA, (const ulonglong2*)xqB,
                          iaA, iaB);
                #pragma unroll
                for (int r = 0; r < 4; r++) {
                    i0t[r]     = tanhf(hadd2(iaA[r]) + c_bin0);
                    i0t[4 + r] = tanhf(hadd2(iaB[r]) + c_bin0);
                }
            }
            {
                float hv[4], hw[4];
                #pragma unroll
                for (int r = 0; r < 4; r++) {
                    hv[r] = hown[r]     * sigmoidf_(avLo[r] + c_battn);
                    hw[r] = hown[4 + r] * sigmoidf_(avHi[r] + c_battn);
                }
                writePair(ha0A, j, hv);
                writePair(ha0B, j, hw);
            }
            barx(1);

            // ---- C: rec0 ----
            float rv[BB];
            {
                ull xA[4] = {0,0,0,0}, xB[4] = {0,0,0,0};
                ull yA[4] = {0,0,0,0}, yB[4] = {0,0,0,0};
                gemm2x<32>(WC + j, WC + jx,
                           (const ulonglong2*)ha0A + s * 128,
                           (const ulonglong2*)ha0B + s * 128,
                           xA, xB, yA, yB);
                combineShfl(xA, yA, rv);
                combineShfl(xB, yB, rv + 4);
            }

            // ---- D: cell0 + LN0 + folded ew1 logit (two quad passes) ----
            float v0[BB], h0n[BB];
            #pragma unroll
            for (int r = 0; r < BB; r++) {
                float h = hown[r];
                v0[r] = h + it * (-h + i0t[r] + tanhf(rv[r] + c_brec)) * (1.f + e0r[r]);
            }
            #pragma unroll
            for (int q = 0; q < 2; q++) {
                float vals[16];
                #pragma unroll
                for (int r = 0; r < 4; r++) {
                    int rr = 4 * q + r;
                    vals[4 * r + 0] = v0[rr];
                    vals[4 * r + 1] = v0[rr] * v0[rr];
                    vals[4 * r + 2] = v0[rr] * gw;
                    vals[4 * r + 3] = hown[rr] * wv1b;
                }
                group_reduce<16>(vals, 1, j, red, stat);
                float hq[4];
                #pragma unroll
                for (int r = 0; r < 4; r++) {
                    float mu  = stat[4 * r] * (1.f / H);
                    float var = stat[4 * r + 1] * (1.f / H) - mu * mu;
                    hq[r] = (v0[4 * q + r] - mu) * rsqrtf(var + EPSC) * c_g + c_b;
                    h0n[4 * q + r] = hq[r];
                }
                writePair(q ? h0nxtB : h0nxtA, j, hq);
                if (j < 4) {
                    int r = j;
                    float mu  = stat[4 * r] * (1.f / H);
                    float var = stat[4 * r + 1] * (1.f / H) - mu * mu;
                    float rs  = rsqrtf(var + EPSC);
                    float lg  = rs * (stat[4 * r + 2] - mu * C2) + C3 + stat[4 * r + 3] + c_bev1;
                    float e   = (t > 0) ? sigmoidf_(lg) : 0.f;
                    ew1_s[4 * q + r] = e;
                    ew1_all[(size_t)(row0 + 4 * q + r) * TT + t] = e;
                }
            }
            __syncthreads();   // FULL1: h0nxt + ew1_s -> g1

            // ---- E: skip ----
            {
                ull xA[4] = {0,0,0,0}, xB[4] = {0,0,0,0};
                ull yA[4] = {0,0,0,0}, yB[4] = {0,0,0,0};
                gemm2x<32>(WE + j, WE + jx,
                           (const ulonglong2*)h0nxtA + s * 128,
                           (const ulonglong2*)h0nxtB + s * 128,
                           xA, xB, yA, yB);
                float svLo[4], svHi[4];
                combineShfl(xA, yA, svLo);
                combineShfl(xB, yB, svHi);
                *(float4*)(skpA + j * 4) = make_float4(svLo[0] + c_bskip, svLo[1] + c_bskip,
                                                       svLo[2] + c_bskip, svLo[3] + c_bskip);
                *(float4*)(skpB + j * 4) = make_float4(svHi[0] + c_bskip, svHi[1] + c_bskip,
                                                       svHi[2] + c_bskip, svHi[3] + c_bskip);
            }
            __syncthreads();   // FULL2: skp -> g1

            #pragma unroll
            for (int r = 0; r < BB; r++) hown[r] = h0n[r];
        } else {
            // ---- B: attn1 ----
            barx(2);           // orders prev-step h1nxt write -> read
            float avLo[4], avHi[4];
            {
                ull xA[4] = {0,0,0,0}, xB[4] = {0,0,0,0};
                ull yA[4] = {0,0,0,0}, yB[4] = {0,0,0,0};
                gemm2x<32>(WB + j, WB + jx,
                           (const ulonglong2*)h1curA + s * 128,
                           (const ulonglong2*)h1curB + s * 128,
                           xA, xB, yA, yB);
                combineShfl(xA, yA, avLo);
                combineShfl(xB, yB, avHi);
            }
            {
                float hv[4], hw[4];
                #pragma unroll
                for (int r = 0; r < 4; r++) {
                    hv[r] = hown[r]     * sigmoidf_(avLo[r] + c_battn);
                    hw[r] = hown[4 + r] * sigmoidf_(avHi[r] + c_battn);
                }
                writePair(ha1A, j, hv);
                writePair(ha1B, j, hw);
            }
            barx(2);

            // ---- C: rec1 ----
            float t_rc1[BB];
            {
                ull xA[4] = {0,0,0,0}, xB[4] = {0,0,0,0};
                ull yA[4] = {0,0,0,0}, yB[4] = {0,0,0,0};
                gemm2x<32>(WC + j, WC + jx,
                           (const ulonglong2*)ha1A + s * 128,
                           (const ulonglong2*)ha1B + s * 128,
                           xA, xB, yA, yB);
                float rv[BB];
                combineShfl(xA, yA, rv);
                combineShfl(xB, yB, rv + 4);
                #pragma unroll
                for (int r = 0; r < BB; r++) t_rc1[r] = tanhf(rv[r] + c_brec);
            }

            __syncthreads();   // FULL1: wait h0nxt + ew1_s

            // ---- E: in1 ----
            float i1t[BB];
            {
                ull xA[4] = {0,0,0,0}, xB[4] = {0,0,0,0};
                ull yA[4] = {0,0,0,0}, yB[4] = {0,0,0,0};
                gemm2x<32>(WE + j, WE + jx,
                           (const ulonglong2*)h0nxtA + s * 128,
                           (const ulonglong2*)h0nxtB + s * 128,
                           xA, xB, yA, yB);
                float iv[BB];
                combineShfl(xA, yA, iv);
                combineShfl(xB, yB, iv + 4);
                #pragma unroll
                for (int r = 0; r < BB; r++) i1t[r] = tanhf(iv[r] + c_bin1);
            }

            __syncthreads();   // FULL2: wait skp

            // ---- F: cell1 + LN1 + skip ----
            float4 skLo = *(const float4*)(skpA + j * 4);
            float4 skHi = *(const float4*)(skpB + j * 4);
            float skv[BB] = { skLo.x, skLo.y, skLo.z, skLo.w,
                              skHi.x, skHi.y, skHi.z, skHi.w };
            float v1[BB], vf[16];
            #pragma unroll
            for (int r = 0; r < BB; r++) {
                float h = hown[r];
                v1[r] = h + it * (-h + i1t[r] + t_rc1[r]) * (1.f + ew1_s[r]);
                vf[2 * r]     = v1[r];
                vf[2 * r + 1] = v1[r] * v1[r];
            }
            group_reduce<16>(vf, 2, j, red, stat);
            float hqA[4], hqB[4];
            #pragma unroll
            for (int r = 0; r < BB; r++) {
                float mu  = stat[2 * r] * (1.f / H);
                float var = stat[2 * r + 1] * (1.f / H) - mu * mu;
                hown[r] = (v1[r] - mu) * rsqrtf(var + EPSC) * c_g + c_b + skv[r];
                if (r < 4) hqA[r] = hown[r]; else hqB[r - 4] = hown[r];
            }
            writePair(h1nxtA, j, hqA);
            writePair(h1nxtB, j, hqB);
            // next step's barx(2) orders these writes
        }
    }

    // ---- Final readout: out[b] = h1 @ Wout + bout (g1) ----
    __syncthreads();
    if (g == 1) {
        float oc[BB];
        #pragma unroll
        for (int r = 0; r < BB; r++) oc[r] = hown[r] * c_wout;
        group_reduce<8>(oc, 2, j, red, stat);
        if (j < BB) out[row0 + j] = stat[j] + bout[0];
    }
}

extern "C" void kernel_launch(void* const* d_in, const int* in_sizes, int n_in,
                              void* d_out, int out_size) {
    const float* x      = (const float*)d_in[0];
    const float* Win0   = (const float*)d_in[1];
    const float* bin0   = (const float*)d_in[2];
    const float* Wrec0  = (const float*)d_in[3];
    const float* brec0  = (const float*)d_in[4];
    const float* Wattn0 = (const float*)d_in[5];
    const float* battn0 = (const float*)d_in[6];
    const float* Wev0   = (const float*)d_in[7];
    const float* bev0   = (const float*)d_in[8];
    const float* tau0   = (const float*)d_in[9];
    const float* gamma0 = (const float*)d_in[10];
    const float* beta0  = (const float*)d_in[11];
    const float* Win1   = (const float*)d_in[12];
    const float* bin1   = (const float*)d_in[13];
    const float* Wrec1  = (const float*)d_in[14];
    const float* brec1  = (const float*)d_in[15];
    const float* Wattn1 = (const float*)d_in[16];
    const float* battn1 = (const float*)d_in[17];
    const float* Wev1   = (const float*)d_in[18];
    const float* bev1   = (const float*)d_in[19];
    const float* tau1   = (const float*)d_in[20];
    const float* gamma1 = (const float*)d_in[21];
    const float* beta1  = (const float*)d_in[22];
    const float* Wskip  = (const float*)d_in[23];
    const float* bskip  = (const float*)d_in[24];
    const float* Wout   = (const float*)d_in[25];
    const float* bout   = (const float*)d_in[26];

    float* out = (float*)d_out;
    float* ew0 = out + BATCH;
    float* ew1 = ew0 + (size_t)BATCH * TT;

    const int TOT = 6 * H * H + INP * H;
    transpose_kernel<<<(TOT + 255) / 256, 256>>>(Wattn0, Wattn1, Wrec0, Wrec1,
                                                 Win1, Wskip, Win0);
    ew0_kernel<<<(BATCH * TT + 255) / 256, 256>>>(x, Wev0, bev0, ew0);

    static int smem_set = 0;
    if (!smem_set) {
        cudaFuncSetAttribute(liquid_kernel,
                             cudaFuncAttributeMaxDynamicSharedMemorySize,
                             SMEM_BYTES);
        smem_set = 1;
    }

    liquid_kernel<<<GRID, NT, SMEM_BYTES>>>(
        x, bin0, brec0, battn0, tau0, gamma0, beta0,
        bin1, brec1, battn1, Wev1, bev1, tau1, gamma1, beta1,
        bskip, Wout, bout,
        out, ew0, ew1);
}

// round 12
// speedup vs baseline: 1.1565x; 1.1565x over previous
#include <cuda_runtime.h>
#include <math.h>

#define BATCH 512
#define TT    2048
#define INP   32
#define H     256
#define DTC   0.1f
#define EPSC  1e-5f
#define BB    8
#define GRID  (BATCH / BB)   /* 64 blocks */
#define NT    512            /* 2 layer-groups x 256 */

typedef unsigned long long ull;

// Transposed-interleaved weight scratch: layout [k/4][j][k&3] per matrix.
#define WOFF_A0 0
#define WOFF_A1 (1 * H * H)
#define WOFF_R0 (2 * H * H)
#define WOFF_R1 (3 * H * H)
#define WOFF_I1 (4 * H * H)
#define WOFF_SK (5 * H * H)
#define WOFF_I0 (6 * H * H)
__device__ __align__(16) float g_Wt[6 * H * H + INP * H];

// Dynamic smem layout (bytes). A = rows 0-3, B = rows 4-7.
#define SM_H0A   0        /* 2 x 4096 ping-pong */
#define SM_H0B   8192     /* 2 x 4096 */
#define SM_H1A   16384    /* 2 x 4096 */
#define SM_H1B   24576    /* 2 x 4096 */
#define SM_HA0A  32768    /* 4096 */
#define SM_HA0B  36864    /* 4096 */
#define SM_HA1A  40960    /* 4096 */
#define SM_HA1B  45056    /* 4096 */
#define SM_SKPA  49152    /* 4096 */
#define SM_SKPB  53248    /* 4096 */
#define SM_XQA   57344    /* 512 */
#define SM_XQB   57856    /* 512 */
#define SM_RED0  58368    /* 512 */
#define SM_RED1  58880    /* 512 */
#define SM_STAT0 59392    /* 64 */
#define SM_STAT1 59456    /* 64 */
#define SM_EW1   59520    /* 32 */
#define SMEM_BYTES 59648

__device__ __forceinline__ float sigmoidf_(float v) {
    return 1.0f / (1.0f + expf(-v));
}
__device__ __forceinline__ void ffma2(ull& d, ull a, ull b) {
    asm("fma.rn.f32x2 %0, %1, %2, %0;" : "+l"(d) : "l"(a), "l"(b));
}
__device__ __forceinline__ ull fadd2(ull a, ull b) {
    ull r; asm("add.rn.f32x2 %0, %1, %2;" : "=l"(r) : "l"(a), "l"(b)); return r;
}
__device__ __forceinline__ float hadd2(ull a) {
    float lo, hi; asm("mov.b64 {%0, %1}, %2;" : "=f"(lo), "=f"(hi) : "l"(a));
    return lo + hi;
}
__device__ __forceinline__ void barx(int id) {
    asm volatile("bar.sync %0, %1;" :: "r"(id), "r"(256) : "memory");
}

// Group-local reduction over 8 warps of NV values -> stat[0..NV-1].
template <int NV>
__device__ __forceinline__ void group_reduce(float* vals, int barid, int gt,
                                             float (*red)[16], float* stat) {
    #pragma unroll
    for (int o = 16; o > 0; o >>= 1) {
        #pragma unroll
        for (int i = 0; i < NV; i++)
            vals[i] += __shfl_xor_sync(0xffffffffu, vals[i], o);
    }
    int w = gt >> 5, l = gt & 31;
    if (l == 0) {
        #pragma unroll
        for (int i = 0; i < NV; i++) red[w][i] = vals[i];
    }
    barx(barid);
    if (gt < NV) {
        float a = 0.f;
        #pragma unroll
        for (int w2 = 0; w2 < 8; w2++) a += red[w2][gt];
        stat[gt] = a;
    }
    barx(barid);
}

// Write unit-j row values v[0..3] into pair-interleaved layout:
// buf[p*8 + {0..3}] = (h_2p[r0], h_2p+1[r0], h_2p[r1], h_2p+1[r1]); +4 = r2,r3.
__device__ __forceinline__ void writePair(float* buf, int j, const float* v) {
    float o0 = __shfl_xor_sync(0xffffffffu, v[0], 1);
    float o1 = __shfl_xor_sync(0xffffffffu, v[1], 1);
    float o2 = __shfl_xor_sync(0xffffffffu, v[2], 1);
    float o3 = __shfl_xor_sync(0xffffffffu, v[3], 1);
    int p = j >> 1;
    if ((j & 1) == 0) *(float4*)(buf + p * 8)     = make_float4(v[0], o0, v[1], o1);
    else              *(float4*)(buf + p * 8 + 4) = make_float4(o2, v[2], o3, v[3]);
}

// Dual-column GEMM over NCH 4-k chunks, shared weights across TWO row-quads.
// Weights: packed (w_k,w_k+1) pairs, coalesced LDG.128, prefetch distance 1.
// h: pair-layout smem (quad A rows 0-3, quad B rows 4-7).
// xA/yA: colX/colY accs rows0-3; xB/yB: rows4-7. Summation order per row
// identical to the BB=4 version (bit-exact numerics per batch row).
template <int NCH>
__device__ __forceinline__ void gemm2x(const ulonglong2* __restrict__ wX,
                                       const ulonglong2* __restrict__ wY,
                                       const ulonglong2* __restrict__ hA,
                                       const ulonglong2* __restrict__ hB,
                                       ull* xA, ull* xB, ull* yA, ull* yB) {
    ulonglong2 wx = __ldg(wX), wy = __ldg(wY);
    #pragma unroll 2
    for (int i = 0; i < NCH; i++) {
        ulonglong2 cwx = wx, cwy = wy;
        if (i + 1 < NCH) {
            wx = __ldg(wX + (i + 1) * 256);
            wy = __ldg(wY + (i + 1) * 256);
        }
        ulonglong2 a0 = hA[4 * i],     a1 = hA[4 * i + 1];
        ulonglong2 a2 = hA[4 * i + 2], a3 = hA[4 * i + 3];
        ulonglong2 b0 = hB[4 * i],     b1 = hB[4 * i + 1];
        ulonglong2 b2 = hB[4 * i + 2], b3 = hB[4 * i + 3];
        ffma2(xA[0], a0.x, cwx.x); ffma2(xA[1], a0.y, cwx.x);
        ffma2(xA[2], a1.x, cwx.x); ffma2(xA[3], a1.y, cwx.x);
        ffma2(xA[0], a2.x, cwx.y); ffma2(xA[1], a2.y, cwx.y);
        ffma2(xA[2], a3.x, cwx.y); ffma2(xA[3], a3.y, cwx.y);
        ffma2(xB[0], b0.x, cwx.x); ffma2(xB[1], b0.y, cwx.x);
        ffma2(xB[2], b1.x, cwx.x); ffma2(xB[3], b1.y, cwx.x);
        ffma2(xB[0], b2.x, cwx.y); ffma2(xB[1], b2.y, cwx.y);
        ffma2(xB[2], b3.x, cwx.y); ffma2(xB[3], b3.y, cwx.y);
        ffma2(yA[0], a0.x, cwy.x); ffma2(yA[1], a0.y, cwy.x);
        ffma2(yA[2], a1.x, cwy.x); ffma2(yA[3], a1.y, cwy.x);
        ffma2(yA[0], a2.x, cwy.y); ffma2(yA[1], a2.y, cwy.y);
        ffma2(yA[2], a3.x, cwy.y); ffma2(yA[3], a3.y, cwy.y);
        ffma2(yB[0], b0.x, cwy.x); ffma2(yB[1], b0.y, cwy.x);
        ffma2(yB[2], b1.x, cwy.x); ffma2(yB[3], b1.y, cwy.x);
        ffma2(yB[0], b2.x, cwy.y); ffma2(yB[1], b2.y, cwy.y);
        ffma2(yB[2], b3.x, cwy.y); ffma2(yB[3], b3.y, cwy.y);
    }
}

// Single-column GEMM, shared weights across two row-quads (for in0, full k).
template <int NCH>
__device__ __forceinline__ void gemm1x(const ulonglong2* __restrict__ wp,
                                       const ulonglong2* __restrict__ hA,
                                       const ulonglong2* __restrict__ hB,
                                       ull* accA, ull* accB) {
    ulonglong2 n = __ldg(wp);
    #pragma unroll
    for (int i = 0; i < NCH; i++) {
        ulonglong2 w = n;
        if (i + 1 < NCH) n = __ldg(wp + (i + 1) * 256);
        ulonglong2 a0 = hA[4 * i],     a1 = hA[4 * i + 1];
        ulonglong2 a2 = hA[4 * i + 2], a3 = hA[4 * i + 3];
        ulonglong2 b0 = hB[4 * i],     b1 = hB[4 * i + 1];
        ulonglong2 b2 = hB[4 * i + 2], b3 = hB[4 * i + 3];
        ffma2(accA[0], a0.x, w.x); ffma2(accA[1], a0.y, w.x);
        ffma2(accA[2], a1.x, w.x); ffma2(accA[3], a1.y, w.x);
        ffma2(accA[0], a2.x, w.y); ffma2(accA[1], a2.y, w.y);
        ffma2(accA[2], a3.x, w.y); ffma2(accA[3], a3.y, w.y);
        ffma2(accB[0], b0.x, w.x); ffma2(accB[1], b0.y, w.x);
        ffma2(accB[2], b1.x, w.x); ffma2(accB[3], b1.y, w.x);
        ffma2(accB[0], b2.x, w.y); ffma2(accB[1], b2.y, w.y);
        ffma2(accB[2], b3.x, w.y); ffma2(accB[3], b3.y, w.y);
    }
}

// Exchange colY partials with same-warp partner (lane j^16) and finish col-j
// sums for one row-quad. No barrier, no smem: pure warp shuffle.
__device__ __forceinline__ void combineShfl(const ull* aX, const ull* aY, float* res) {
    #pragma unroll
    for (int r = 0; r < 4; r++) {
        ull p = __shfl_xor_sync(0xffffffffu, aY[r], 16);
        res[r] = hadd2(fadd2(aX[r], p));
    }
}

// ---------------------------------------------------------------------------
// Kernel 0: transpose weights into [k/4][j][k&3] interleaved layout.
// ---------------------------------------------------------------------------
__global__ void transpose_kernel(
    const float* __restrict__ A0, const float* __restrict__ A1,
    const float* __restrict__ R0, const float* __restrict__ R1,
    const float* __restrict__ I1, const float* __restrict__ SK,
    const float* __restrict__ I0)
{
    int idx = blockIdx.x * blockDim.x + threadIdx.x;
    const int BIG = 6 * H * H;
    if (idx < BIG) {
        int m = idx >> 16, rem = idx & 65535;
        int k = rem >> 8, j = rem & 255;
        const float* src = (m == 0) ? A0 : (m == 1) ? A1 : (m == 2) ? R0
                         : (m == 3) ? R1 : (m == 4) ? I1 : SK;
        g_Wt[(m << 16) + (k >> 2) * (H * 4) + j * 4 + (k & 3)] = src[rem];
    } else if (idx < BIG + INP * H) {
        int rem = idx - BIG;
        int k = rem >> 8, j = rem & 255;
        g_Wt[BIG + (k >> 2) * (H * 4) + j * 4 + (k & 3)] = I0[rem];
    }
}

// ---------------------------------------------------------------------------
// Kernel 1: ew0[b,t] = mask * sigmoid([x_t, x_{t-1}] @ Wev0 + bev0)
// ---------------------------------------------------------------------------
__global__ void ew0_kernel(const float* __restrict__ x,
                           const float* __restrict__ Wev0,
                           const float* __restrict__ bev0,
                           float* __restrict__ ew0_out) {
    int idx = blockIdx.x * blockDim.x + threadIdx.x;
    if (idx >= BATCH * TT) return;
    int t = idx & (TT - 1);
    float r = 0.f;
    if (t > 0) {
        const float* xc = x + (size_t)idx * INP;
        const float* xp = xc - INP;
        float s = bev0[0];
        #pragma unroll
        for (int i = 0; i < INP; i++) s += xc[i] * Wev0[i];
        #pragma unroll
        for (int i = 0; i < INP; i++) s += xp[i] * Wev0[INP + i];
        r = sigmoidf_(s);
    }
    ew0_out[idx] = r;
}

// ---------------------------------------------------------------------------
// Kernel 2: persistent recurrence. 8 batch rows/block (two quads sharing
// every weight fetch -> half the L2 weight traffic of BB=4).
// 512 threads = 2 layer-groups x 256 units. Thread j computes cols {j, j^16}
// over k-half ((j>>4)&1); partner in-warp; combine via shfl.
// ---------------------------------------------------------------------------
__global__ __launch_bounds__(NT, 1) void liquid_kernel(
    const float* __restrict__ x,
    const float* __restrict__ bin0,  const float* __restrict__ brec0,
    const float* __restrict__ battn0,
    const float* __restrict__ tau0,  const float* __restrict__ gamma0, const float* __restrict__ beta0,
    const float* __restrict__ bin1,  const float* __restrict__ brec1,
    const float* __restrict__ battn1,
    const float* __restrict__ Wev1,  const float* __restrict__ bev1,
    const float* __restrict__ tau1,  const float* __restrict__ gamma1, const float* __restrict__ beta1,
    const float* __restrict__ bskip,
    const float* __restrict__ Wout,  const float* __restrict__ bout,
    float* __restrict__ out,
    const float* __restrict__ ew0_all,
    float* __restrict__ ew1_all)
{
    extern __shared__ __align__(16) char smraw[];

    const int tid  = threadIdx.x;
    const int g    = tid >> 8;        // layer-group
    const int j    = tid & 255;       // unit / group-local tid
    const int s    = (j >> 4) & 1;    // k-half (partner j^16 in same warp)
    const int row0 = blockIdx.x * BB;
    const int barid = 1 + g;

    float* ha0A = (float*)(smraw + SM_HA0A);
    float* ha0B = (float*)(smraw + SM_HA0B);
    float* ha1A = (float*)(smraw + SM_HA1A);
    float* ha1B = (float*)(smraw + SM_HA1B);
    float* skpA = (float*)(smraw + SM_SKPA);
    float* skpB = (float*)(smraw + SM_SKPB);
    float* xqA  = (float*)(smraw + SM_XQA);
    float* xqB  = (float*)(smraw + SM_XQB);
    float (*red)[16] = (float (*)[16])(smraw + (g ? SM_RED1 : SM_RED0));
    float* stat      = (float*)(smraw + (g ? SM_STAT1 : SM_STAT0));
    float* ew1_s     = (float*)(smraw + SM_EW1);

    // ---- per-group constants ----
    float c_battn, c_brec, it, c_g, c_b;
    float c_bin0 = 0.f, c_bin1 = 0.f, wv1a = 0.f, wv1b = 0.f, c_bev1 = 0.f;
    float c_bskip = 0.f, c_wout = 0.f;
    if (g == 0) {
        c_battn = battn0[j]; c_brec = brec0[j];
        it = DTC / fminf(fmaxf(tau0[j], 0.1f), 10.0f);
        c_g = gamma0[j]; c_b = beta0[j];
        c_bin0 = bin0[j]; c_bskip = bskip[j];
        wv1a = Wev1[j]; wv1b = Wev1[H + j]; c_bev1 = bev1[0];
    } else {
        c_battn = battn1[j]; c_brec = brec1[j];
        it = DTC / fminf(fmaxf(tau1[j], 0.1f), 10.0f);
        c_g = gamma1[j]; c_b = beta1[j];
        c_bin1 = bin1[j]; c_wout = Wout[j];
    }
    const float gw = c_g * wv1a;

    float C2 = 0.f, C3 = 0.f;
    if (g == 0) {
        float cc[2] = { gw, c_b * wv1a };
        group_reduce<2>(cc, barid, j, red, stat);
        C2 = stat[0]; C3 = stat[1];
    }

    // Weight bases: matrix base + k-half offset (ulonglong2 units).
    const int so = s * 32 * 256;
    const ulonglong2* WB = (const ulonglong2*)(g_Wt + (g ? WOFF_A1 : WOFF_A0)) + so;
    const ulonglong2* WC = (const ulonglong2*)(g_Wt + (g ? WOFF_R1 : WOFF_R0)) + so;
    const ulonglong2* WE = (const ulonglong2*)(g_Wt + (g ? WOFF_I1 : WOFF_SK)) + so;
    const ulonglong2* WI = (const ulonglong2*)(g_Wt + WOFF_I0) + j;
    const int jx = j ^ 16;

    float hown[BB] = {0.f, 0.f, 0.f, 0.f, 0.f, 0.f, 0.f, 0.f};
    if (g == 0) {
        *(float4*)((float*)(smraw + SM_H0A) + j * 4) = make_float4(0.f, 0.f, 0.f, 0.f);
        *(float4*)((float*)(smraw + SM_H0B) + j * 4) = make_float4(0.f, 0.f, 0.f, 0.f);
    } else {
        *(float4*)((float*)(smraw + SM_H1A) + j * 4) = make_float4(0.f, 0.f, 0.f, 0.f);
        *(float4*)((float*)(smraw + SM_H1B) + j * 4) = make_float4(0.f, 0.f, 0.f, 0.f);
    }
    __syncthreads();

    for (int t = 0; t < TT; t++) {
        const int co = (t & 1) * 4096, no = co ^ 4096;
        float* h0curA = (float*)(smraw + SM_H0A + co);
        float* h0curB = (float*)(smraw + SM_H0B + co);
        float* h1curA = (float*)(smraw + SM_H1A + co);
        float* h1curB = (float*)(smraw + SM_H1B + co);
        float* h0nxtA = (float*)(smraw + SM_H0A + no);
        float* h0nxtB = (float*)(smraw + SM_H0B + no);
        float* h1nxtA = (float*)(smraw + SM_H1A + no);
        float* h1nxtB = (float*)(smraw + SM_H1B + no);

        if (g == 0) {
            // ---- A: ew0 + x_t staging ----
            float e0r[BB];
            #pragma unroll
            for (int r = 0; r < BB; r++)
                e0r[r] = ew0_all[(size_t)(row0 + r) * TT + t];
            if (j < INP) {
                float xv[4], xw[4];
                #pragma unroll
                for (int r = 0; r < 4; r++)
                    xv[r] = x[((size_t)(row0 + r) * TT + t) * INP + j];
                #pragma unroll
                for (int r = 0; r < 4; r++)
                    xw[r] = x[((size_t)(row0 + 4 + r) * TT + t) * INP + j];
                writePair(xqA, j, xv);
                writePair(xqB, j, xw);
            }
            barx(1);

            // ---- B: attn0 (dual-col, two quads) + in0 ----
            float avLo[4], avHi[4];
            {
                ull xA[4] = {0,0,0,0}, xB[4] = {0,0,0,0};
                ull yA[4] = {0,0,0,0}, yB[4] = {0,0,0,0};
                gemm2x<32>(WB + j, WB + jx,
                           (const ulonglong2*)h0curA + s * 128,
                           (const ulonglong2*)h0curB + s * 128,
                           xA, xB, yA, yB);
                combineShfl(xA, yA, avLo);
                combineShfl(xB, yB, avHi);
            }
            float i0t[BB];
            {
                ull iaA[4] = {0,0,0,0}, iaB[4] = {0,0,0,0};
                gemm1x<8>(WI, (const ulonglong2*)xqA, (const ulonglong2*)xqB,
                          iaA, iaB);
                #pragma unroll
                for (int r = 0; r < 4; r++) {
                    i0t[r]     = tanhf(hadd2(iaA[r]) + c_bin0);
                    i0t[4 + r] = tanhf(hadd2(iaB[r]) + c_bin0);
                }
            }
            {
                float hv[4], hw[4];
                #pragma unroll
                for (int r = 0; r < 4; r++) {
                    hv[r] = hown[r]     * sigmoidf_(avLo[r] + c_battn);
                    hw[r] = hown[4 + r] * sigmoidf_(avHi[r] + c_battn);
                }
                writePair(ha0A, j, hv);
                writePair(ha0B, j, hw);
            }
            barx(1);

            // ---- C: rec0 ----
            float rv[BB];
            {
                ull xA[4] = {0,0,0,0}, xB[4] = {0,0,0,0};
                ull yA[4] = {0,0,0,0}, yB[4] = {0,0,0,0};
                gemm2x<32>(WC + j, WC + jx,
                           (const ulonglong2*)ha0A + s * 128,
                           (const ulonglong2*)ha0B + s * 128,
                           xA, xB, yA, yB);
                combineShfl(xA, yA, rv);
                combineShfl(xB, yB, rv + 4);
            }

            // ---- D: cell0 + LN0 + folded ew1 logit (two quad passes) ----
            float v0[BB], h0n[BB];
            #pragma unroll
            for (int r = 0; r < BB; r++) {
                float h = hown[r];
                v0[r] = h + it * (-h + i0t[r] + tanhf(rv[r] + c_brec)) * (1.f + e0r[r]);
            }
            #pragma unroll
            for (int q = 0; q < 2; q++) {
                float vals[16];
                #pragma unroll
                for (int r = 0; r < 4; r++) {
                    int rr = 4 * q + r;
                    vals[4 * r + 0] = v0[rr];
                    vals[4 * r + 1] = v0[rr] * v0[rr];
                    vals[4 * r + 2] = v0[rr] * gw;
                    vals[4 * r + 3] = hown[rr] * wv1b;
                }
                group_reduce<16>(vals, 1, j, red, stat);
                float hq[4];
                #pragma unroll
                for (int r = 0; r < 4; r++) {
                    float mu  = stat[4 * r] * (1.f / H);
                    float var = stat[4 * r + 1] * (1.f / H) - mu * mu;
                    hq[r] = (v0[4 * q + r] - mu) * rsqrtf(var + EPSC) * c_g + c_b;
                    h0n[4 * q + r] = hq[r];
                }
                writePair(q ? h0nxtB : h0nxtA, j, hq);
                if (j < 4) {
                    int r = j;
                    float mu  = stat[4 * r] * (1.f / H);
                    float var = stat[4 * r + 1] * (1.f / H) - mu * mu;
                    float rs  = rsqrtf(var + EPSC);
                    float lg  = rs * (stat[4 * r + 2] - mu * C2) + C3 + stat[4 * r + 3] + c_bev1;
                    float e   = (t > 0) ? sigmoidf_(lg) : 0.f;
                    ew1_s[4 * q + r] = e;
                    ew1_all[(size_t)(row0 + 4 * q + r) * TT + t] = e;
                }
            }
            __syncthreads();   // FULL1: h0nxt + ew1_s -> g1

            // ---- E: skip ----
            {
                ull xA[4] = {0,0,0,0}, xB[4] = {0,0,0,0};
                ull yA[4] = {0,0,0,0}, yB[4] = {0,0,0,0};
                gemm2x<32>(WE + j, WE + jx,
                           (const ulonglong2*)h0nxtA + s * 128,
                           (const ulonglong2*)h0nxtB + s * 128,
                           xA, xB, yA, yB);
                float svLo[4], svHi[4];
                combineShfl(xA, yA, svLo);
                combineShfl(xB, yB, svHi);
                *(float4*)(skpA + j * 4) = make_float4(svLo[0] + c_bskip, svLo[1] + c_bskip,
                                                       svLo[2] + c_bskip, svLo[3] + c_bskip);
                *(float4*)(skpB + j * 4) = make_float4(svHi[0] + c_bskip, svHi[1] + c_bskip,
                                                       svHi[2] + c_bskip, svHi[3] + c_bskip);
            }
            __syncthreads();   // FULL2: skp -> g1

            #pragma unroll
            for (int r = 0; r < BB; r++) hown[r] = h0n[r];
        } else {
            // ---- B: attn1 ----
            barx(2);           // orders prev-step h1nxt write -> read
            float avLo[4], avHi[4];
            {
                ull xA[4] = {0,0,0,0}, xB[4] = {0,0,0,0};
                ull yA[4] = {0,0,0,0}, yB[4] = {0,0,0,0};
                gemm2x<32>(WB + j, WB + jx,
                           (const ulonglong2*)h1curA + s * 128,
                           (const ulonglong2*)h1curB + s * 128,
                           xA, xB, yA, yB);
                combineShfl(xA, yA, avLo);
                combineShfl(xB, yB, avHi);
            }
            {
                float hv[4], hw[4];
                #pragma unroll
                for (int r = 0; r < 4; r++) {
                    hv[r] = hown[r]     * sigmoidf_(avLo[r] + c_battn);
                    hw[r] = hown[4 + r] * sigmoidf_(avHi[r] + c_battn);
                }
                writePair(ha1A, j, hv);
                writePair(ha1B, j, hw);
            }
            barx(2);

            // ---- C: rec1 ----
            float t_rc1[BB];
            {
                ull xA[4] = {0,0,0,0}, xB[4] = {0,0,0,0};
                ull yA[4] = {0,0,0,0}, yB[4] = {0,0,0,0};
                gemm2x<32>(WC + j, WC + jx,
                           (const ulonglong2*)ha1A + s * 128,
                           (const ulonglong2*)ha1B + s * 128,
                           xA, xB, yA, yB);
                float rv[BB];
                combineShfl(xA, yA, rv);
                combineShfl(xB, yB, rv + 4);
                #pragma unroll
                for (int r = 0; r < BB; r++) t_rc1[r] = tanhf(rv[r] + c_brec);
            }

            __syncthreads();   // FULL1: wait h0nxt + ew1_s

            // ---- E: in1 ----
            float i1t[BB];
            {
                ull xA[4] = {0,0,0,0}, xB[4] = {0,0,0,0};
                ull yA[4] = {0,0,0,0}, yB[4] = {0,0,0,0};
                gemm2x<32>(WE + j, WE + jx,
                           (const ulonglong2*)h0nxtA + s * 128,
                           (const ulonglong2*)h0nxtB + s * 128,
                           xA, xB, yA, yB);
                float iv[BB];
                combineShfl(xA, yA, iv);
                combineShfl(xB, yB, iv + 4);
                #pragma unroll
                for (int r = 0; r < BB; r++) i1t[r] = tanhf(iv[r] + c_bin1);
            }

            __syncthreads();   // FULL2: wait skp

            // ---- F: cell1 + LN1 + skip ----
            float4 skLo = *(const float4*)(skpA + j * 4);
            float4 skHi = *(const float4*)(skpB + j * 4);
            float skv[BB] = { skLo.x, skLo.y, skLo.z, skLo.w,
                              skHi.x, skHi.y, skHi.z, skHi.w };
            float v1[BB], vf[16];
            #pragma unroll
            for (int r = 0; r < BB; r++) {
                float h = hown[r];
                v1[r] = h + it * (-h + i1t[r] + t_rc1[r]) * (1.f + ew1_s[r]);
                vf[2 * r]     = v1[r];
                vf[2 * r + 1] = v1[r] * v1[r];
            }
            group_reduce<16>(vf, 2, j, red, stat);
            float hqA[4], hqB[4];
            #pragma unroll
            for (int r = 0; r < BB; r++) {
                float mu  = stat[2 * r] * (1.f / H);
                float var = stat[2 * r + 1] * (1.f / H) - mu * mu;
                hown[r] = (v1[r] - mu) * rsqrtf(var + EPSC) * c_g + c_b + skv[r];
                if (r < 4) hqA[r] = hown[r]; else hqB[r - 4] = hown[r];
            }
            writePair(h1nxtA, j, hqA);
            writePair(h1nxtB, j, hqB);
            // next step's barx(2) orders these writes
        }
    }

    // ---- Final readout: out[b] = h1 @ Wout + bout (g1) ----
    __syncthreads();
    if (g == 1) {
        float oc[BB];
        #pragma unroll
        for (int r = 0; r < BB; r++) oc[r] = hown[r] * c_wout;
        group_reduce<8>(oc, 2, j, red, stat);
        if (j < BB) out[row0 + j] = stat[j] + bout[0];
    }
}

extern "C" void kernel_launch(void* const* d_in, const int* in_sizes, int n_in,
                              void* d_out, int out_size) {
    const float* x      = (const float*)d_in[0];
    const float* Win0   = (const float*)d_in[1];
    const float* bin0   = (const float*)d_in[2];
    const float* Wrec0  = (const float*)d_in[3];
    const float* brec0  = (const float*)d_in[4];
    const float* Wattn0 = (const float*)d_in[5];
    const float* battn0 = (const float*)d_in[6];
    const float* Wev0   = (const float*)d_in[7];
    const float* bev0   = (const float*)d_in[8];
    const float* tau0   = (const float*)d_in[9];
    const float* gamma0 = (const float*)d_in[10];
    const float* beta0  = (const float*)d_in[11];
    const float* Win1   = (const float*)d_in[12];
    const float* bin1   = (const float*)d_in[13];
    const float* Wrec1  = (const float*)d_in[14];
    const float* brec1  = (const float*)d_in[15];
    const float* Wattn1 = (const float*)d_in[16];
    const float* battn1 = (const float*)d_in[17];
    const float* Wev1   = (const float*)d_in[18];
    const float* bev1   = (const float*)d_in[19];
    const float* tau1   = (const float*)d_in[20];
    const float* gamma1 = (const float*)d_in[21];
    const float* beta1  = (const float*)d_in[22];
    const float* Wskip  = (const float*)d_in[23];
    const float* bskip  = (const float*)d_in[24];
    const float* Wout   = (const float*)d_in[25];
    const float* bout   = (const float*)d_in[26];

    float* out = (float*)d_out;
    float* ew0 = out + BATCH;
    float* ew1 = ew0 + (size_t)BATCH * TT;

    const int TOT = 6 * H * H + INP * H;
    transpose_kernel<<<(TOT + 255) / 256, 256>>>(Wattn0, Wattn1, Wrec0, Wrec1,
                                                 Win1, Wskip, Win0);
    ew0_kernel<<<(BATCH * TT + 255) / 256, 256>>>(x, Wev0, bev0, ew0);

    static int smem_set = 0;
    if (!smem_set) {
        cudaFuncSetAttribute(liquid_kernel,
                             cudaFuncAttributeMaxDynamicSharedMemorySize,
                             SMEM_BYTES);
        smem_set = 1;
    }

    liquid_kernel<<<GRID, NT, SMEM_BYTES>>>(
        x, bin0, brec0, battn0, tau0, gamma0, beta0,
        bin1, brec1, battn1, Wev1, bev1, tau1, gamma1, beta1,
        bskip, Wout, bout,
        out, ew0, ew1);
}

// round 13
// speedup vs baseline: 1.2479x; 1.0790x over previous
#include <cuda_runtime.h>
#include <math.h>

#define BATCH 512
#define TT    2048
#define INP   32
#define H     256
#define DTC   0.1f
#define EPSC  1e-5f
#define BB    8
#define GRID  ((BATCH / BB) * 2)   /* 128 CTAs = 64 clusters x 2 */
#define NT    512                  /* 2 layer-groups x 256 */

typedef unsigned long long ull;

// Transposed-interleaved weight scratch: layout [k/4][j][k&3] per matrix.
#define WOFF_A0 0
#define WOFF_A1 (1 * H * H)
#define WOFF_R0 (2 * H * H)
#define WOFF_R1 (3 * H * H)
#define WOFF_I1 (4 * H * H)
#define WOFF_SK (5 * H * H)
#define WOFF_I0 (6 * H * H)
__device__ __align__(16) float g_Wt[6 * H * H + INP * H];

// Dynamic smem layout (bytes). A = rows 0-3, B = rows 4-7.
#define SM_H0A   0        /* 2 x 4096 ping-pong */
#define SM_H0B   8192
#define SM_H1A   16384
#define SM_H1B   24576
#define SM_HA0A  32768
#define SM_HA0B  36864
#define SM_HA1A  40960
#define SM_HA1B  45056
#define SM_SKPA  49152
#define SM_SKPB  53248
#define SM_XQA   57344
#define SM_XQB   57856
#define SM_RED0  58368
#define SM_RED1  58880
#define SM_STAT0 59392
#define SM_STAT1 59456
#define SM_EW1   59520
#define SM_EXG   59648    /* 6 buffers x 8192: (g*3 + slot) */
#define SM_MBARC 108800   /* 6 mbarriers x 8B */
#define SMEM_BYTES 108864

__device__ __forceinline__ float sigmoidf_(float v) {
    return 1.0f / (1.0f + expf(-v));
}
__device__ __forceinline__ void ffma2(ull& d, ull a, ull b) {
    asm("fma.rn.f32x2 %0, %1, %2, %0;" : "+l"(d) : "l"(a), "l"(b));
}
__device__ __forceinline__ float hadd2(ull a) {
    float lo, hi; asm("mov.b64 {%0, %1}, %2;" : "=f"(lo), "=f"(hi) : "l"(a));
    return lo + hi;
}
__device__ __forceinline__ void barx(int id) {
    asm volatile("bar.sync %0, %1;" :: "r"(id), "r"(256) : "memory");
}
__device__ __forceinline__ unsigned smem_u32(const void* p) {
    unsigned a;
    asm("{ .reg .u64 t; cvta.to.shared.u64 t, %1; cvt.u32.u64 %0, t; }"
        : "=r"(a) : "l"(p));
    return a;
}

// Group-local reduction over 8 warps of NV values -> stat[0..NV-1].
template <int NV>
__device__ __forceinline__ void group_reduce(float* vals, int barid, int gt,
                                             float (*red)[16], float* stat) {
    #pragma unroll
    for (int o = 16; o > 0; o >>= 1) {
        #pragma unroll
        for (int i = 0; i < NV; i++)
            vals[i] += __shfl_xor_sync(0xffffffffu, vals[i], o);
    }
    int w = gt >> 5, l = gt & 31;
    if (l == 0) {
        #pragma unroll
        for (int i = 0; i < NV; i++) red[w][i] = vals[i];
    }
    barx(barid);
    if (gt < NV) {
        float a = 0.f;
        #pragma unroll
        for (int w2 = 0; w2 < 8; w2++) a += red[w2][gt];
        stat[gt] = a;
    }
    barx(barid);
}

// Write unit-j row values v[0..3] into pair-interleaved layout.
__device__ __forceinline__ void writePair(float* buf, int j, const float* v) {
    float o0 = __shfl_xor_sync(0xffffffffu, v[0], 1);
    float o1 = __shfl_xor_sync(0xffffffffu, v[1], 1);
    float o2 = __shfl_xor_sync(0xffffffffu, v[2], 1);
    float o3 = __shfl_xor_sync(0xffffffffu, v[3], 1);
    int p = j >> 1;
    if ((j & 1) == 0) *(float4*)(buf + p * 8)     = make_float4(v[0], o0, v[1], o1);
    else              *(float4*)(buf + p * 8 + 4) = make_float4(o2, v[2], o3, v[3]);
}

// Single-column GEMM over NCH 4-k chunks for unit j, two row-quads sharing
// each weight fetch. Weights: packed (w_k,w_k+1) pairs, coalesced LDG.128,
// PF-deep circular prefetch. h from pair-layout smem.
template <int NCH, int PF>
__device__ __forceinline__ void gemmS(const ulonglong2* __restrict__ wp,
                                      const ulonglong2* __restrict__ hA,
                                      const ulonglong2* __restrict__ hB,
                                      ull* aA, ull* aB) {
    ulonglong2 wbuf[PF];
    #pragma unroll
    for (int p = 0; p < PF; p++) wbuf[p] = __ldg(wp + p * 256);
    #pragma unroll 4
    for (int i = 0; i < NCH; i++) {
        ulonglong2 w = wbuf[i % PF];
        if (i + PF < NCH) wbuf[i % PF] = __ldg(wp + (i + PF) * 256);
        ulonglong2 a0 = hA[4 * i],     a1 = hA[4 * i + 1];
        ulonglong2 a2 = hA[4 * i + 2], a3 = hA[4 * i + 3];
        ulonglong2 b0 = hB[4 * i],     b1 = hB[4 * i + 1];
        ulonglong2 b2 = hB[4 * i + 2], b3 = hB[4 * i + 3];
        ffma2(aA[0], a0.x, w.x); ffma2(aA[1], a0.y, w.x);
        ffma2(aA[2], a1.x, w.x); ffma2(aA[3], a1.y, w.x);
        ffma2(aB[0], b0.x, w.x); ffma2(aB[1], b0.y, w.x);
        ffma2(aB[2], b1.x, w.x); ffma2(aB[3], b1.y, w.x);
        ffma2(aA[0], a2.x, w.y); ffma2(aA[1], a2.y, w.y);
        ffma2(aA[2], a3.x, w.y); ffma2(aA[3], a3.y, w.y);
        ffma2(aB[0], b2.x, w.y); ffma2(aB[1], b2.y, w.y);
        ffma2(aB[2], b3.x, w.y); ffma2(aB[3], b3.y, w.y);
    }
}

// Cross-CTA combine of half-k partials: write own half to own smem slot,
// group barrier, arrive on peer's mbarrier, wait own mbarrier (parity t&1),
// DSMEM-read peer half, add. fp-add commutativity => both CTAs identical.
__device__ __forceinline__ void clusterExchange(char* smraw, unsigned smb,
                                                int g, int sl, int j, int rank,
                                                unsigned parity, float* res) {
    const int boff = SM_EXG + (g * 3 + sl) * 8192 + j * 32;
    float* buf = (float*)(smraw + boff);
    *(float4*)buf       = make_float4(res[0], res[1], res[2], res[3]);
    *(float4*)(buf + 4) = make_float4(res[4], res[5], res[6], res[7]);
    barx(1 + g);
    const unsigned mbar = smb + SM_MBARC + (g * 3 + sl) * 8;
    if (j == 0) {
        asm volatile("fence.acq_rel.cluster;" ::: "memory");
        unsigned rm;
        asm volatile("mapa.shared::cluster.u32 %0, %1, %2;"
                     : "=r"(rm) : "r"(mbar), "r"(rank ^ 1));
        asm volatile("mbarrier.arrive.shared::cluster.b64 _, [%0];"
                     :: "r"(rm) : "memory");
    }
    asm volatile(
        "{\n\t.reg .pred P;\n"
        "WL_%=:\n\t"
        "mbarrier.try_wait.parity.shared.b64 P, [%0], %1, 0x989680;\n\t"
        "@!P bra WL_%=;\n\t}"
        :: "r"(mbar), "r"(parity) : "memory");
    asm volatile("fence.acq_rel.cluster;" ::: "memory");
    unsigned rb;
    asm volatile("mapa.shared::cluster.u32 %0, %1, %2;"
                 : "=r"(rb) : "r"(smb + boff), "r"(rank ^ 1));
    float p0, p1, p2, p3, p4, p5, p6, p7;
    asm volatile("ld.shared::cluster.v4.f32 {%0,%1,%2,%3}, [%4];"
                 : "=f"(p0), "=f"(p1), "=f"(p2), "=f"(p3) : "r"(rb));
    asm volatile("ld.shared::cluster.v4.f32 {%0,%1,%2,%3}, [%4];"
                 : "=f"(p4), "=f"(p5), "=f"(p6), "=f"(p7) : "r"(rb + 16));
    res[0] += p0; res[1] += p1; res[2] += p2; res[3] += p3;
    res[4] += p4; res[5] += p5; res[6] += p6; res[7] += p7;
}

// ---------------------------------------------------------------------------
// Kernel 0: transpose weights into [k/4][j][k&3] interleaved layout.
// ---------------------------------------------------------------------------
__global__ void transpose_kernel(
    const float* __restrict__ A0, const float* __restrict__ A1,
    const float* __restrict__ R0, const float* __restrict__ R1,
    const float* __restrict__ I1, const float* __restrict__ SK,
    const float* __restrict__ I0)
{
    int idx = blockIdx.x * blockDim.x + threadIdx.x;
    const int BIG = 6 * H * H;
    if (idx < BIG) {
        int m = idx >> 16, rem = idx & 65535;
        int k = rem >> 8, j = rem & 255;
        const float* src = (m == 0) ? A0 : (m == 1) ? A1 : (m == 2) ? R0
                         : (m == 3) ? R1 : (m == 4) ? I1 : SK;
        g_Wt[(m << 16) + (k >> 2) * (H * 4) + j * 4 + (k & 3)] = src[rem];
    } else if (idx < BIG + INP * H) {
        int rem = idx - BIG;
        int k = rem >> 8, j = rem & 255;
        g_Wt[BIG + (k >> 2) * (H * 4) + j * 4 + (k & 3)] = I0[rem];
    }
}

// ---------------------------------------------------------------------------
// Kernel 1: ew0[b,t] = mask * sigmoid([x_t, x_{t-1}] @ Wev0 + bev0)
// ---------------------------------------------------------------------------
__global__ void ew0_kernel(const float* __restrict__ x,
                           const float* __restrict__ Wev0,
                           const float* __restrict__ bev0,
                           float* __restrict__ ew0_out) {
    int idx = blockIdx.x * blockDim.x + threadIdx.x;
    if (idx >= BATCH * TT) return;
    int t = idx & (TT - 1);
    float r = 0.f;
    if (t > 0) {
        const float* xc = x + (size_t)idx * INP;
        const float* xp = xc - INP;
        float s = bev0[0];
        #pragma unroll
        for (int i = 0; i < INP; i++) s += xc[i] * Wev0[i];
        #pragma unroll
        for (int i = 0; i < INP; i++) s += xp[i] * Wev0[INP + i];
        r = sigmoidf_(s);
    }
    ew0_out[idx] = r;
}

// ---------------------------------------------------------------------------
// Kernel 2: persistent recurrence. 2-CTA clusters: cluster owns 8 batch rows;
// each CTA computes all 256 columns over HALF the k-range of every HxH GEMM
// (halves L2 weight traffic at full 128-CTA occupancy); half-k partials are
// combined via DSMEM + mbarriers. Within CTA: 2 layer-groups x 256 units.
// ---------------------------------------------------------------------------
__global__ __launch_bounds__(NT, 1) __cluster_dims__(2, 1, 1)
void liquid_kernel(
    const float* __restrict__ x,
    const float* __restrict__ bin0,  const float* __restrict__ brec0,
    const float* __restrict__ battn0,
    const float* __restrict__ tau0,  const float* __restrict__ gamma0, const float* __restrict__ beta0,
    const float* __restrict__ bin1,  const float* __restrict__ brec1,
    const float* __restrict__ battn1,
    const float* __restrict__ Wev1,  const float* __restrict__ bev1,
    const float* __restrict__ tau1,  const float* __restrict__ gamma1, const float* __restrict__ beta1,
    const float* __restrict__ bskip,
    const float* __restrict__ Wout,  const float* __restrict__ bout,
    float* __restrict__ out,
    const float* __restrict__ ew0_all,
    float* __restrict__ ew1_all)
{
    extern __shared__ __align__(16) char smraw[];

    const int tid  = threadIdx.x;
    const int g    = tid >> 8;              // layer-group
    const int j    = tid & 255;             // unit / group-local tid
    const int rank = blockIdx.x & 1;        // k-half owner within cluster
    const int row0 = (blockIdx.x >> 1) * BB;
    const int barid = 1 + g;
    const unsigned smb = smem_u32(smraw);

    float* ha0A = (float*)(smraw + SM_HA0A);
    float* ha0B = (float*)(smraw + SM_HA0B);
    float* ha1A = (float*)(smraw + SM_HA1A);
    float* ha1B = (float*)(smraw + SM_HA1B);
    float* skpA = (float*)(smraw + SM_SKPA);
    float* skpB = (float*)(smraw + SM_SKPB);
    float* xqA  = (float*)(smraw + SM_XQA);
    float* xqB  = (float*)(smraw + SM_XQB);
    float (*red)[16] = (float (*)[16])(smraw + (g ? SM_RED1 : SM_RED0));
    float* stat      = (float*)(smraw + (g ? SM_STAT1 : SM_STAT0));
    float* ew1_s     = (float*)(smraw + SM_EW1);

    // ---- per-group constants ----
    float c_battn, c_brec, it, c_g, c_b;
    float c_bin0 = 0.f, c_bin1 = 0.f, wv1a = 0.f, wv1b = 0.f, c_bev1 = 0.f;
    float c_bskip = 0.f, c_wout = 0.f;
    if (g == 0) {
        c_battn = battn0[j]; c_brec = brec0[j];
        it = DTC / fminf(fmaxf(tau0[j], 0.1f), 10.0f);
        c_g = gamma0[j]; c_b = beta0[j];
        c_bin0 = bin0[j]; c_bskip = bskip[j];
        wv1a = Wev1[j]; wv1b = Wev1[H + j]; c_bev1 = bev1[0];
    } else {
        c_battn = battn1[j]; c_brec = brec1[j];
        it = DTC / fminf(fmaxf(tau1[j], 0.1f), 10.0f);
        c_g = gamma1[j]; c_b = beta1[j];
        c_bin1 = bin1[j]; c_wout = Wout[j];
    }
    const float gw = c_g * wv1a;

    // mbarrier init (6 = group * 3 + slot), then cluster-wide visibility.
    if (tid == 0) {
        #pragma unroll
        for (int i = 0; i < 6; i++) {
            unsigned mb = smb + SM_MBARC + i * 8;
            asm volatile("mbarrier.init.shared.b64 [%0], %1;"
                         :: "r"(mb), "r"(1u) : "memory");
        }
    }
    __syncthreads();
    asm volatile("barrier.cluster.arrive.aligned;" ::: "memory");
    asm volatile("barrier.cluster.wait.aligned;" ::: "memory");

    float C2 = 0.f, C3 = 0.f;
    if (g == 0) {
        float cc[2] = { gw, c_b * wv1a };
        group_reduce<2>(cc, barid, j, red, stat);
        C2 = stat[0]; C3 = stat[1];
    }

    // Weight bases: matrix base + k-half offset + column (ulonglong2 units).
    const int so = rank * 32 * 256;
    const ulonglong2* WB = (const ulonglong2*)(g_Wt + (g ? WOFF_A1 : WOFF_A0)) + so + j;
    const ulonglong2* WC = (const ulonglong2*)(g_Wt + (g ? WOFF_R1 : WOFF_R0)) + so + j;
    const ulonglong2* WE = (const ulonglong2*)(g_Wt + (g ? WOFF_I1 : WOFF_SK)) + so + j;
    const ulonglong2* WI = (const ulonglong2*)(g_Wt + WOFF_I0) + j;
    const int hko = rank * 128;   // k-half offset into pair-layout h (ulonglong2)

    float hown[BB] = {0.f, 0.f, 0.f, 0.f, 0.f, 0.f, 0.f, 0.f};
    if (g == 0) {
        *(float4*)((float*)(smraw + SM_H0A) + j * 4) = make_float4(0.f, 0.f, 0.f, 0.f);
        *(float4*)((float*)(smraw + SM_H0B) + j * 4) = make_float4(0.f, 0.f, 0.f, 0.f);
    } else {
        *(float4*)((float*)(smraw + SM_H1A) + j * 4) = make_float4(0.f, 0.f, 0.f, 0.f);
        *(float4*)((float*)(smraw + SM_H1B) + j * 4) = make_float4(0.f, 0.f, 0.f, 0.f);
    }
    __syncthreads();

    for (int t = 0; t < TT; t++) {
        const unsigned par = (unsigned)(t & 1);
        const int co = (t & 1) * 4096, no = co ^ 4096;
        float* h0curA = (float*)(smraw + SM_H0A + co);
        float* h0curB = (float*)(smraw + SM_H0B + co);
        float* h1curA = (float*)(smraw + SM_H1A + co);
        float* h1curB = (float*)(smraw + SM_H1B + co);
        float* h0nxtA = (float*)(smraw + SM_H0A + no);
        float* h0nxtB = (float*)(smraw + SM_H0B + no);
        float* h1nxtA = (float*)(smraw + SM_H1A + no);
        float* h1nxtB = (float*)(smraw + SM_H1B + no);

        if (g == 0) {
            // ---- A: ew0 + x_t staging ----
            float e0r[BB];
            #pragma unroll
            for (int r = 0; r < BB; r++)
                e0r[r] = ew0_all[(size_t)(row0 + r) * TT + t];
            if (j < INP) {
                float xv[4], xw[4];
                #pragma unroll
                for (int r = 0; r < 4; r++)
                    xv[r] = x[((size_t)(row0 + r) * TT + t) * INP + j];
                #pragma unroll
                for (int r = 0; r < 4; r++)
                    xw[r] = x[((size_t)(row0 + 4 + r) * TT + t) * INP + j];
                writePair(xqA, j, xv);
                writePair(xqB, j, xw);
            }
            barx(1);

            // ---- B: attn0 (half-k + exchange) + in0 (full-k, tiny) ----
            float av[8];
            {
                ull aA[4] = {0,0,0,0}, aB[4] = {0,0,0,0};
                gemmS<32, 4>(WB, (const ulonglong2*)h0curA + hko,
                             (const ulonglong2*)h0curB + hko, aA, aB);
                #pragma unroll
                for (int r = 0; r < 4; r++) { av[r] = hadd2(aA[r]); av[4 + r] = hadd2(aB[r]); }
            }
            clusterExchange(smraw, smb, 0, 0, j, rank, par, av);

            float i0t[BB];
            {
                ull iaA[4] = {0,0,0,0}, iaB[4] = {0,0,0,0};
                gemmS<8, 4>(WI, (const ulonglong2*)xqA, (const ulonglong2*)xqB, iaA, iaB);
                #pragma unroll
                for (int r = 0; r < 4; r++) {
                    i0t[r]     = tanhf(hadd2(iaA[r]) + c_bin0);
                    i0t[4 + r] = tanhf(hadd2(iaB[r]) + c_bin0);
                }
            }
            {
                float hv[4], hw[4];
                #pragma unroll
                for (int r = 0; r < 4; r++) {
                    hv[r] = hown[r]     * sigmoidf_(av[r] + c_battn);
                    hw[r] = hown[4 + r] * sigmoidf_(av[4 + r] + c_battn);
                }
                writePair(ha0A, j, hv);
                writePair(ha0B, j, hw);
            }
            barx(1);

            // ---- C: rec0 ----
            float rv[BB];
            {
                ull rA[4] = {0,0,0,0}, rB[4] = {0,0,0,0};
                gemmS<32, 4>(WC, (const ulonglong2*)ha0A + hko,
                             (const ulonglong2*)ha0B + hko, rA, rB);
                #pragma unroll
                for (int r = 0; r < 4; r++) { rv[r] = hadd2(rA[r]); rv[4 + r] = hadd2(rB[r]); }
            }
            clusterExchange(smraw, smb, 0, 1, j, rank, par, rv);

            // ---- D: cell0 + LN0 + folded ew1 logit (two quad passes) ----
            float v0[BB], h0n[BB];
            #pragma unroll
            for (int r = 0; r < BB; r++) {
                float h = hown[r];
                v0[r] = h + it * (-h + i0t[r] + tanhf(rv[r] + c_brec)) * (1.f + e0r[r]);
            }
            #pragma unroll
            for (int q = 0; q < 2; q++) {
                float vals[16];
                #pragma unroll
                for (int r = 0; r < 4; r++) {
                    int rr = 4 * q + r;
                    vals[4 * r + 0] = v0[rr];
                    vals[4 * r + 1] = v0[rr] * v0[rr];
                    vals[4 * r + 2] = v0[rr] * gw;
                    vals[4 * r + 3] = hown[rr] * wv1b;
                }
                group_reduce<16>(vals, 1, j, red, stat);
                float hq[4];
                #pragma unroll
                for (int r = 0; r < 4; r++) {
                    float mu  = stat[4 * r] * (1.f / H);
                    float var = stat[4 * r + 1] * (1.f / H) - mu * mu;
                    hq[r] = (v0[4 * q + r] - mu) * rsqrtf(var + EPSC) * c_g + c_b;
                    h0n[4 * q + r] = hq[r];
                }
                writePair(q ? h0nxtB : h0nxtA, j, hq);
                if (j < 4) {
                    int r = j;
                    float mu  = stat[4 * r] * (1.f / H);
                    float var = stat[4 * r + 1] * (1.f / H) - mu * mu;
                    float rs  = rsqrtf(var + EPSC);
                    float lg  = rs * (stat[4 * r + 2] - mu * C2) + C3 + stat[4 * r + 3] + c_bev1;
                    float e   = (t > 0) ? sigmoidf_(lg) : 0.f;
                    ew1_s[4 * q + r] = e;
                    if (rank == 0)
                        ew1_all[(size_t)(row0 + 4 * q + r) * TT + t] = e;
                }
            }
            __syncthreads();   // FULL1: h0nxt + ew1_s -> g1

            // ---- E: skip ----
            float sv[BB];
            {
                ull sA[4] = {0,0,0,0}, sB[4] = {0,0,0,0};
                gemmS<32, 4>(WE, (const ulonglong2*)h0nxtA + hko,
                             (const ulonglong2*)h0nxtB + hko, sA, sB);
                #pragma unroll
                for (int r = 0; r < 4; r++) { sv[r] = hadd2(sA[r]); sv[4 + r] = hadd2(sB[r]); }
            }
            clusterExchange(smraw, smb, 0, 2, j, rank, par, sv);
            *(float4*)(skpA + j * 4) = make_float4(sv[0] + c_bskip, sv[1] + c_bskip,
                                                   sv[2] + c_bskip, sv[3] + c_bskip);
            *(float4*)(skpB + j * 4) = make_float4(sv[4] + c_bskip, sv[5] + c_bskip,
                                                   sv[6] + c_bskip, sv[7] + c_bskip);
            __syncthreads();   // FULL2: skp -> g1

            #pragma unroll
            for (int r = 0; r < BB; r++) hown[r] = h0n[r];
        } else {
            // ---- B: attn1 ----
            barx(2);           // orders prev-step h1nxt write -> read
            float av[8];
            {
                ull aA[4] = {0,0,0,0}, aB[4] = {0,0,0,0};
                gemmS<32, 4>(WB, (const ulonglong2*)h1curA + hko,
                             (const ulonglong2*)h1curB + hko, aA, aB);
                #pragma unroll
                for (int r = 0; r < 4; r++) { av[r] = hadd2(aA[r]); av[4 + r] = hadd2(aB[r]); }
            }
            clusterExchange(smraw, smb, 1, 0, j, rank, par, av);
            {
                float hv[4], hw[4];
                #pragma unroll
                for (int r = 0; r < 4; r++) {
                    hv[r] = hown[r]     * sigmoidf_(av[r] + c_battn);
                    hw[r] = hown[4 + r] * sigmoidf_(av[4 + r] + c_battn);
                }
                writePair(ha1A, j, hv);
                writePair(ha1B, j, hw);
            }
            barx(2);

            // ---- C: rec1 ----
            float t_rc1[BB];
            {
                ull rA[4] = {0,0,0,0}, rB[4] = {0,0,0,0};
                gemmS<32, 4>(WC, (const ulonglong2*)ha1A + hko,
                             (const ulonglong2*)ha1B + hko, rA, rB);
                float rv[BB];
                #pragma unroll
                for (int r = 0; r < 4; r++) { rv[r] = hadd2(rA[r]); rv[4 + r] = hadd2(rB[r]); }
                clusterExchange(smraw, smb, 1, 1, j, rank, par, rv);
                #pragma unroll
                for (int r = 0; r < BB; r++) t_rc1[r] = tanhf(rv[r] + c_brec);
            }

            __syncthreads();   // FULL1: wait h0nxt + ew1_s

            // ---- E: in1 ----
            float i1t[BB];
            {
                ull iA[4] = {0,0,0,0}, iB[4] = {0,0,0,0};
                gemmS<32, 4>(WE, (const ulonglong2*)h0nxtA + hko,
                             (const ulonglong2*)h0nxtB + hko, iA, iB);
                float iv[BB];
                #pragma unroll
                for (int r = 0; r < 4; r++) { iv[r] = hadd2(iA[r]); iv[4 + r] = hadd2(iB[r]); }
                clusterExchange(smraw, smb, 1, 2, j, rank, par, iv);
                #pragma unroll
                for (int r = 0; r < BB; r++) i1t[r] = tanhf(iv[r] + c_bin1);
            }

            __syncthreads();   // FULL2: wait skp

            // ---- F: cell1 + LN1 + skip ----
            float4 skLo = *(const float4*)(skpA + j * 4);
            float4 skHi = *(const float4*)(skpB + j * 4);
            float skv[BB] = { skLo.x, skLo.y, skLo.z, skLo.w,
                              skHi.x, skHi.y, skHi.z, skHi.w };
            float v1[BB], vf[16];
            #pragma unroll
            for (int r = 0; r < BB; r++) {
                float h = hown[r];
                v1[r] = h + it * (-h + i1t[r] + t_rc1[r]) * (1.f + ew1_s[r]);
                vf[2 * r]     = v1[r];
                vf[2 * r + 1] = v1[r] * v1[r];
            }
            group_reduce<16>(vf, 2, j, red, stat);
            float hqA[4], hqB[4];
            #pragma unroll
            for (int r = 0; r < BB; r++) {
                float mu  = stat[2 * r] * (1.f / H);
                float var = stat[2 * r + 1] * (1.f / H) - mu * mu;
                hown[r] = (v1[r] - mu) * rsqrtf(var + EPSC) * c_g + c_b + skv[r];
                if (r < 4) hqA[r] = hown[r]; else hqB[r - 4] = hown[r];
            }
            writePair(h1nxtA, j, hqA);
            writePair(h1nxtB, j, hqB);
            // next step's barx(2) orders these writes
        }
    }

    // ---- Final readout: out[b] = h1 @ Wout + bout (g1; rank 0 stores) ----
    __syncthreads();
    if (g == 1) {
        float oc[BB];
        #pragma unroll
        for (int r = 0; r < BB; r++) oc[r] = hown[r] * c_wout;
        group_reduce<8>(oc, 2, j, red, stat);
        if (j < BB && rank == 0) out[row0 + j] = stat[j] + bout[0];
    }

    // Keep both CTAs resident until all DSMEM traffic has completed.
    asm volatile("barrier.cluster.arrive.aligned;" ::: "memory");
    asm volatile("barrier.cluster.wait.aligned;" ::: "memory");
}

extern "C" void kernel_launch(void* const* d_in, const int* in_sizes, int n_in,
                              void* d_out, int out_size) {
    const float* x      = (const float*)d_in[0];
    const float* Win0   = (const float*)d_in[1];
    const float* bin0   = (const float*)d_in[2];
    const float* Wrec0  = (const float*)d_in[3];
    const float* brec0  = (const float*)d_in[4];
    const float* Wattn0 = (const float*)d_in[5];
    const float* battn0 = (const float*)d_in[6];
    const float* Wev0   = (const float*)d_in[7];
    const float* bev0   = (const float*)d_in[8];
    const float* tau0   = (const float*)d_in[9];
    const float* gamma0 = (const float*)d_in[10];
    const float* beta0  = (const float*)d_in[11];
    const float* Win1   = (const float*)d_in[12];
    const float* bin1   = (const float*)d_in[13];
    const float* Wrec1  = (const float*)d_in[14];
    const float* brec1  = (const float*)d_in[15];
    const float* Wattn1 = (const float*)d_in[16];
    const float* battn1 = (const float*)d_in[17];
    const float* Wev1   = (const float*)d_in[18];
    const float* bev1   = (const float*)d_in[19];
    const float* tau1   = (const float*)d_in[20];
    const float* gamma1 = (const float*)d_in[21];
    const float* beta1  = (const float*)d_in[22];
    const float* Wskip  = (const float*)d_in[23];
    const float* bskip  = (const float*)d_in[24];
    const float* Wout   = (const float*)d_in[25];
    const float* bout   = (const float*)d_in[26];

    float* out = (float*)d_out;
    float* ew0 = out + BATCH;
    float* ew1 = ew0 + (size_t)BATCH * TT;

    const int TOT = 6 * H * H + INP * H;
    transpose_kernel<<<(TOT + 255) / 256, 256>>>(Wattn0, Wattn1, Wrec0, Wrec1,
                                                 Win1, Wskip, Win0);
    ew0_kernel<<<(BATCH * TT + 255) / 256, 256>>>(x, Wev0, bev0, ew0);

    static int smem_set = 0;
    if (!smem_set) {
        cudaFuncSetAttribute(liquid_kernel,
                             cudaFuncAttributeMaxDynamicSharedMemorySize,
                             SMEM_BYTES);
        smem_set = 1;
    }

    liquid_kernel<<<GRID, NT, SMEM_BYTES>>>(
        x, bin0, brec0, battn0, tau0, gamma0, beta0,
        bin1, brec1, battn1, Wev1, bev1, tau1, gamma1, beta1,
        bskip, Wout, bout,
        out, ew0, ew1);
}

// round 16
// speedup vs baseline: 1.4745x; 1.1816x over previous
#include <cuda_runtime.h>
#include <math.h>

#define BATCH 512
#define TT    2048
#define INP   32
#define H     256
#define DTC   0.1f
#define EPSC  1e-5f
#define BB    4
#define GRID  (BATCH / BB)   /* 128 blocks */
#define NT    512            /* 2 layer-groups x 256 */
#define NSMC  3              /* weight chunks per matrix-half resident in smem */

typedef unsigned long long ull;

// Transposed-interleaved weight scratch: layout [k/4][j][k&3] per matrix.
#define WOFF_A0 0
#define WOFF_A1 (1 * H * H)
#define WOFF_R0 (2 * H * H)
#define WOFF_R1 (3 * H * H)
#define WOFF_I1 (4 * H * H)
#define WOFF_SK (5 * H * H)
#define WOFF_I0 (6 * H * H)
__device__ __align__(16) float g_Wt[6 * H * H + INP * H];

// Dynamic smem layout (bytes)
#define SM_H0Q   0        /* 2 x 4096 ping-pong */
#define SM_H1Q   8192     /* 2 x 4096 */
#define SM_HA0   16384    /* 4096 */
#define SM_HA1   20480    /* 4096 */
#define SM_SKP   24576    /* 4096 */
#define SM_XQ    28672    /* 512 */
#define SM_RED0  29184    /* 512 */
#define SM_RED1  29696    /* 512 */
#define SM_STAT0 30208    /* 64 */
#define SM_STAT1 30272    /* 64 */
#define SM_EW1   30336    /* 16 + pad */
#define SM_WBIG  30720    /* 6 mat x 2 half x NSMC chunks x 4KB = 147456 */
#define SM_WI0   178176   /* Win0: 8 chunks x 4KB = 32768 */
#define SMEM_BYTES 210944

__device__ __forceinline__ float sigmoidf_(float v) {
    return 1.0f / (1.0f + expf(-v));
}
__device__ __forceinline__ void ffma2(ull& d, ull a, ull b) {
    asm("fma.rn.f32x2 %0, %1, %2, %0;" : "+l"(d) : "l"(a), "l"(b));
}
__device__ __forceinline__ ull fadd2(ull a, ull b) {
    ull r; asm("add.rn.f32x2 %0, %1, %2;" : "=l"(r) : "l"(a), "l"(b)); return r;
}
__device__ __forceinline__ float hadd2(ull a) {
    float lo, hi; asm("mov.b64 {%0, %1}, %2;" : "=f"(lo), "=f"(hi) : "l"(a));
    return lo + hi;
}
__device__ __forceinline__ void barx(int id) {
    asm volatile("bar.sync %0, %1;" :: "r"(id), "r"(256) : "memory");
}

// Group-local reduction over 8 warps of NV values -> stat[0..NV-1].
template <int NV>
__device__ __forceinline__ void group_reduce(float* vals, int barid, int gt,
                                             float (*red)[16], float* stat) {
    #pragma unroll
    for (int o = 16; o > 0; o >>= 1) {
        #pragma unroll
        for (int i = 0; i < NV; i++)
            vals[i] += __shfl_xor_sync(0xffffffffu, vals[i], o);
    }
    int w = gt >> 5, l = gt & 31;
    if (l == 0) {
        #pragma unroll
        for (int i = 0; i < NV; i++) red[w][i] = vals[i];
    }
    barx(barid);
    if (gt < NV) {
        float a = 0.f;
        #pragma unroll
        for (int w2 = 0; w2 < 8; w2++) a += red[w2][gt];
        stat[gt] = a;
    }
    barx(barid);
}

// Write unit-j row values v[0..3] into pair-interleaved layout:
// buf[p*8 + {0..3}] = (h_2p[0], h_2p+1[0], h_2p[1], h_2p+1[1]); +4 = rows 2,3.
__device__ __forceinline__ void writePair(float* buf, int j, const float* v) {
    float o0 = __shfl_xor_sync(0xffffffffu, v[0], 1);
    float o1 = __shfl_xor_sync(0xffffffffu, v[1], 1);
    float o2 = __shfl_xor_sync(0xffffffffu, v[2], 1);
    float o3 = __shfl_xor_sync(0xffffffffu, v[3], 1);
    int p = j >> 1;
    if ((j & 1) == 0) *(float4*)(buf + p * 8)     = make_float4(v[0], o0, v[1], o1);
    else              *(float4*)(buf + p * 8 + 4) = make_float4(o2, v[2], o3, v[3]);
}

#define FFMA_CHUNK(I, CWX, CWY)                                            \
    do {                                                                   \
        ulonglong2 h0 = hq[4 * (I)],     h1 = hq[4 * (I) + 1];             \
        ulonglong2 h2 = hq[4 * (I) + 2], h3 = hq[4 * (I) + 3];             \
        ffma2(aX[0], h0.x, (CWX).x); ffma2(aX[1], h0.y, (CWX).x);          \
        ffma2(aX[2], h1.x, (CWX).x); ffma2(aX[3], h1.y, (CWX).x);          \
        ffma2(aX[0], h2.x, (CWX).y); ffma2(aX[1], h2.y, (CWX).y);          \
        ffma2(aX[2], h3.x, (CWX).y); ffma2(aX[3], h3.y, (CWX).y);          \
        ffma2(aY[0], h0.x, (CWY).x); ffma2(aY[1], h0.y, (CWY).x);          \
        ffma2(aY[2], h1.x, (CWY).x); ffma2(aY[3], h1.y, (CWY).x);          \
        ffma2(aY[0], h2.x, (CWY).y); ffma2(aY[1], h2.y, (CWY).y);          \
        ffma2(aY[2], h3.x, (CWY).y); ffma2(aY[3], h3.y, (CWY).y);          \
    } while (0)

// Dual-column GEMM over NCH 4-k chunks: chunks [0, NSM) read from the smem
// weight cache, chunks [NSM, NCH) from global (coalesced LDG.128, distance-1
// prefetch). Chunk ORDER and FFMA sequence identical to the all-LDG version
// -> bit-identical numerics. h from pair-layout smem.
template <int NCH, int NSM>
__device__ __forceinline__ void gemm2h(const ulonglong2* __restrict__ ws,
                                       int j, int jx,
                                       const ulonglong2* __restrict__ wX,
                                       const ulonglong2* __restrict__ wY,
                                       const ulonglong2* __restrict__ hq,
                                       ull* aX, ull* aY) {
    ulonglong2 wx = __ldg(wX + NSM * 256), wy = __ldg(wY + NSM * 256);
    #pragma unroll
    for (int i = 0; i < NSM; i++) {
        ulonglong2 cwx = ws[i * 256 + j];
        ulonglong2 cwy = ws[i * 256 + jx];
        FFMA_CHUNK(i, cwx, cwy);
    }
    #pragma unroll 4
    for (int i = NSM; i < NCH; i++) {
        ulonglong2 cwx = wx, cwy = wy;
        if (i + 1 < NCH) {
            wx = __ldg(wX + (i + 1) * 256);
            wy = __ldg(wY + (i + 1) * 256);
        }
        FFMA_CHUNK(i, cwx, cwy);
    }
}

// Single-column GEMM (full k) from the smem weight cache — for in0 (INP=32).
template <int NCH>
__device__ __forceinline__ void gemm1s(const ulonglong2* __restrict__ ws, int j,
                                       const ulonglong2* __restrict__ hq,
                                       ull* acc) {
    #pragma unroll
    for (int i = 0; i < NCH; i++) {
        ulonglong2 w = ws[i * 256 + j];
        ulonglong2 h0 = hq[4 * i],     h1 = hq[4 * i + 1];
        ulonglong2 h2 = hq[4 * i + 2], h3 = hq[4 * i + 3];
        ffma2(acc[0], h0.x, w.x); ffma2(acc[1], h0.y, w.x);
        ffma2(acc[2], h1.x, w.x); ffma2(acc[3], h1.y, w.x);
        ffma2(acc[0], h2.x, w.y); ffma2(acc[1], h2.y, w.y);
        ffma2(acc[2], h3.x, w.y); ffma2(acc[3], h3.y, w.y);
    }
}

// Exchange colY partials with same-warp partner (lane j^16) and finish col-j
// sums for 4 rows. No barrier, no smem: pure warp shuffle.
__device__ __forceinline__ void combineShfl(const ull* aX, const ull* aY, float* res) {
    #pragma unroll
    for (int r = 0; r < 4; r++) {
        ull p = __shfl_xor_sync(0xffffffffu, aY[r], 16);
        res[r] = hadd2(fadd2(aX[r], p));
    }
}

// ---------------------------------------------------------------------------
// Kernel 0: transpose weights into [k/4][j][k&3] interleaved layout.
// ---------------------------------------------------------------------------
__global__ void transpose_kernel(
    const float* __restrict__ A0, const float* __restrict__ A1,
    const float* __restrict__ R0, const float* __restrict__ R1,
    const float* __restrict__ I1, const float* __restrict__ SK,
    const float* __restrict__ I0)
{
    int idx = blockIdx.x * blockDim.x + threadIdx.x;
    const int BIG = 6 * H * H;
    if (idx < BIG) {
        int m = idx >> 16, rem = idx & 65535;
        int k = rem >> 8, j = rem & 255;
        const float* src = (m == 0) ? A0 : (m == 1) ? A1 : (m == 2) ? R0
                         : (m == 3) ? R1 : (m == 4) ? I1 : SK;
        g_Wt[(m << 16) + (k >> 2) * (H * 4) + j * 4 + (k & 3)] = src[rem];
    } else if (idx < BIG + INP * H) {
        int rem = idx - BIG;
        int k = rem >> 8, j = rem & 255;
        g_Wt[BIG + (k >> 2) * (H * 4) + j * 4 + (k & 3)] = I0[rem];
    }
}

// ---------------------------------------------------------------------------
// Kernel 1: ew0[b,t] = mask * sigmoid([x_t, x_{t-1}] @ Wev0 + bev0)
// ---------------------------------------------------------------------------
__global__ void ew0_kernel(const float* __restrict__ x,
                           const float* __restrict__ Wev0,
                           const float* __restrict__ bev0,
                           float* __restrict__ ew0_out) {
    int idx = blockIdx.x * blockDim.x + threadIdx.x;
    if (idx >= BATCH * TT) return;
    int t = idx & (TT - 1);
    float r = 0.f;
    if (t > 0) {
        const float* xc = x + (size_t)idx * INP;
        const float* xp = xc - INP;
        float s = bev0[0];
        #pragma unroll
        for (int i = 0; i < INP; i++) s += xc[i] * Wev0[i];
        #pragma unroll
        for (int i = 0; i < INP; i++) s += xp[i] * Wev0[INP + i];
        r = sigmoidf_(s);
    }
    ew0_out[idx] = r;
}

// ---------------------------------------------------------------------------
// Kernel 2: persistent recurrence. 512 threads = 2 layer-groups x 256.
// Thread j computes cols {j, j^16} over k-half ((j>>4)&1); same-warp partner
// j^16 computes the complementary half; partials combined via shfl.
// NEW: first NSMC weight chunks of each matrix-half + all of Win0 live in
// smem (copied once) -> 11% fewer L2 weight bytes per step, identical math.
// ---------------------------------------------------------------------------
__global__ __launch_bounds__(NT, 1) void liquid_kernel(
    const float* __restrict__ x,
    const float* __restrict__ bin0,  const float* __restrict__ brec0,
    const float* __restrict__ battn0,
    const float* __restrict__ tau0,  const float* __restrict__ gamma0, const float* __restrict__ beta0,
    const float* __restrict__ bin1,  const float* __restrict__ brec1,
    const float* __restrict__ battn1,
    const float* __restrict__ Wev1,  const float* __restrict__ bev1,
    const float* __restrict__ tau1,  const float* __restrict__ gamma1, const float* __restrict__ beta1,
    const float* __restrict__ bskip,
    const float* __restrict__ Wout,  const float* __restrict__ bout,
    float* __restrict__ out,
    const float* __restrict__ ew0_all,
    float* __restrict__ ew1_all)
{
    extern __shared__ __align__(16) char smraw[];

    const int tid  = threadIdx.x;
    const int g    = tid >> 8;        // layer-group
    const int j    = tid & 255;       // unit / group-local tid
    const int s    = (j >> 4) & 1;    // k-half (partner j^16 in same warp)
    const int row0 = blockIdx.x * BB;
    const int barid = 1 + g;

    float* ha0q = (float*)(smraw + SM_HA0);
    float* ha1q = (float*)(smraw + SM_HA1);
    float* skp  = (float*)(smraw + SM_SKP);
    float* xq   = (float*)(smraw + SM_XQ);
    float (*red)[16] = (float (*)[16])(smraw + (g ? SM_RED1 : SM_RED0));
    float* stat      = (float*)(smraw + (g ? SM_STAT1 : SM_STAT0));
    float* ew1_s     = (float*)(smraw + SM_EW1);
    ulonglong2* wsm  = (ulonglong2*)(smraw + SM_WBIG);
    ulonglong2* wi0s = (ulonglong2*)(smraw + SM_WI0);

    // ---- per-group constants ----
    float c_battn, c_brec, it, c_g, c_b;
    float c_bin0 = 0.f, c_bin1 = 0.f, wv1a = 0.f, wv1b = 0.f, c_bev1 = 0.f;
    float c_bskip = 0.f, c_wout = 0.f;
    if (g == 0) {
        c_battn = battn0[j]; c_brec = brec0[j];
        it = DTC / fminf(fmaxf(tau0[j], 0.1f), 10.0f);
        c_g = gamma0[j]; c_b = beta0[j];
        c_bin0 = bin0[j]; c_bskip = bskip[j];
        wv1a = Wev1[j]; wv1b = Wev1[H + j]; c_bev1 = bev1[0];
    } else {
        c_battn = battn1[j]; c_brec = brec1[j];
        it = DTC / fminf(fmaxf(tau1[j], 0.1f), 10.0f);
        c_g = gamma1[j]; c_b = beta1[j];
        c_bin1 = bin1[j]; c_wout = Wout[j];
    }
    const float gw = c_g * wv1a;

    float C2 = 0.f, C3 = 0.f;
    if (g == 0) {
        float cc[2] = { gw, c_b * wv1a };
        group_reduce<2>(cc, barid, j, red, stat);
        C2 = stat[0]; C3 = stat[1];
    }

    // ---- one-time smem weight cache fill ----
    {
        const ulonglong2* gwq = (const ulonglong2*)g_Wt;
        #pragma unroll 4
        for (int e = tid; e < 6 * 2 * NSMC * 256; e += NT) {
            int c  = e & 255;
            int i  = (e >> 8) % NSMC;
            int sh = (e >> 8) / NSMC;       // m*2 + half
            int m  = sh >> 1, s2 = sh & 1;
            wsm[e] = gwq[m * 16384 + s2 * (32 * 256) + i * 256 + c];
        }
        #pragma unroll 2
        for (int e = tid; e < 8 * 256; e += NT)
            wi0s[e] = gwq[(WOFF_I0 / 4) + e];
    }

    // Weight bases: matrix base + k-half offset (ulonglong2 units).
    const int so = s * 32 * 256;
    const ulonglong2* WB = (const ulonglong2*)(g_Wt + (g ? WOFF_A1 : WOFF_A0)) + so;
    const ulonglong2* WC = (const ulonglong2*)(g_Wt + (g ? WOFF_R1 : WOFF_R0)) + so;
    const ulonglong2* WE = (const ulonglong2*)(g_Wt + (g ? WOFF_I1 : WOFF_SK)) + so;
    const int jx = j ^ 16;

    // Smem weight cache bases for this thread's matrix+half.
    const int mB = g ? 1 : 0, mC = g ? 3 : 2, mE = g ? 4 : 5;
    const ulonglong2* sB = wsm + (mB * 2 + s) * NSMC * 256;
    const ulonglong2* sC = wsm + (mC * 2 + s) * NSMC * 256;
    const ulonglong2* sE = wsm + (mE * 2 + s) * NSMC * 256;

    float hown[BB] = {0.f, 0.f, 0.f, 0.f};
    if (g == 0) *(float4*)((float*)(smraw + SM_H0Q) + j * 4) = make_float4(0.f, 0.f, 0.f, 0.f);
    else        *(float4*)((float*)(smraw + SM_H1Q) + j * 4) = make_float4(0.f, 0.f, 0.f, 0.f);
    __syncthreads();

    for (int t = 0; t < TT; t++) {
        const int co = (t & 1) * 4096, no = co ^ 4096;
        float* h0cur = (float*)(smraw + SM_H0Q + co);
        float* h1cur = (float*)(smraw + SM_H1Q + co);
        float* h0nxt = (float*)(smraw + SM_H0Q + no);
        float* h1nxt = (float*)(smraw + SM_H1Q + no);
        float* hqcur = g ? h1cur : h0cur;

        if (g == 0) {
            // ---- A: ew0 + x_t staging ----
            float e0r[BB];
            #pragma unroll
            for (int r = 0; r < BB; r++)
                e0r[r] = ew0_all[(size_t)(row0 + r) * TT + t];
            if (j < INP) {
                float xv[4];
                xv[0] = x[((size_t)(row0 + 0) * TT + t) * INP + j];
                xv[1] = x[((size_t)(row0 + 1) * TT + t) * INP + j];
                xv[2] = x[((size_t)(row0 + 2) * TT + t) * INP + j];
                xv[3] = x[((size_t)(row0 + 3) * TT + t) * INP + j];
                writePair(xq, j, xv);
            }
            barx(1);

            // ---- B: attn0 (split, shfl-combined) + in0 (full, smem weights) ----
            ull aX[4] = {0,0,0,0}, aY[4] = {0,0,0,0}, ia[4] = {0,0,0,0};
            gemm2h<32, NSMC>(sB, j, jx, WB + j, WB + jx,
                             (const ulonglong2*)hqcur + s * 128, aX, aY);
            gemm1s<8>(wi0s, j, (const ulonglong2*)xq, ia);
            float av[4];
            combineShfl(aX, aY, av);
            float i0t[BB], hv[4];
            #pragma unroll
            for (int r = 0; r < BB; r++) {
                i0t[r] = tanhf(hadd2(ia[r]) + c_bin0);
                hv[r]  = hown[r] * sigmoidf_(av[r] + c_battn);
            }
            writePair(ha0q, j, hv);
            barx(1);

            // ---- C: rec0 ----
            ull rX[4] = {0,0,0,0}, rY[4] = {0,0,0,0};
            gemm2h<32, NSMC>(sC, j, jx, WC + j, WC + jx,
                             (const ulonglong2*)ha0q + s * 128, rX, rY);
            float rv[4];
            combineShfl(rX, rY, rv);

            // ---- D: cell0 + LN0 + folded ew1 logit ----
            float v0[BB], vals[16];
            #pragma unroll
            for (int r = 0; r < BB; r++) {
                float h = hown[r];
                v0[r] = h + it * (-h + i0t[r] + tanhf(rv[r] + c_brec)) * (1.f + e0r[r]);
                vals[4 * r + 0] = v0[r];
                vals[4 * r + 1] = v0[r] * v0[r];
                vals[4 * r + 2] = v0[r] * gw;
                vals[4 * r + 3] = h * wv1b;
            }
            group_reduce<16>(vals, 1, j, red, stat);

            float h0n[BB];
            #pragma unroll
            for (int r = 0; r < BB; r++) {
                float mu  = stat[4 * r] * (1.f / H);
                float var = stat[4 * r + 1] * (1.f / H) - mu * mu;
                h0n[r] = (v0[r] - mu) * rsqrtf(var + EPSC) * c_g + c_b;
            }
            writePair(h0nxt, j, h0n);
            if (j < BB) {
                int r = j;
                float mu  = stat[4 * r] * (1.f / H);
                float var = stat[4 * r + 1] * (1.f / H) - mu * mu;
                float rs  = rsqrtf(var + EPSC);
                float lg  = rs * (stat[4 * r + 2] - mu * C2) + C3 + stat[4 * r + 3] + c_bev1;
                float e   = (t > 0) ? sigmoidf_(lg) : 0.f;
                ew1_s[r]  = e;
                ew1_all[(size_t)(row0 + r) * TT + t] = e;
            }
            __syncthreads();   // FULL1: h0nxt + ew1_s -> g1

            // ---- E: skip ----
            ull sX[4] = {0,0,0,0}, sY[4] = {0,0,0,0};
            gemm2h<32, NSMC>(sE, j, jx, WE + j, WE + jx,
                             (const ulonglong2*)h0nxt + s * 128, sX, sY);
            float sv[4];
            combineShfl(sX, sY, sv);
            *(float4*)(skp + j * 4) = make_float4(sv[0] + c_bskip, sv[1] + c_bskip,
                                                  sv[2] + c_bskip, sv[3] + c_bskip);
            __syncthreads();   // FULL2: skp -> g1

            #pragma unroll
            for (int r = 0; r < BB; r++) hown[r] = h0n[r];
        } else {
            // ---- B: attn1 ----
            barx(2);           // orders prev-step h1nxt write -> read
            ull aX[4] = {0,0,0,0}, aY[4] = {0,0,0,0};
            gemm2h<32, NSMC>(sB, j, jx, WB + j, WB + jx,
                             (const ulonglong2*)hqcur + s * 128, aX, aY);
            float av[4];
            combineShfl(aX, aY, av);
            float hv[4];
            #pragma unroll
            for (int r = 0; r < BB; r++)
                hv[r] = hown[r] * sigmoidf_(av[r] + c_battn);
            writePair(ha1q, j, hv);
            barx(2);

            // ---- C: rec1 ----
            ull rX[4] = {0,0,0,0}, rY[4] = {0,0,0,0};
            gemm2h<32, NSMC>(sC, j, jx, WC + j, WC + jx,
                             (const ulonglong2*)ha1q + s * 128, rX, rY);
            float rv[4];
            combineShfl(rX, rY, rv);
            float t_rc1[BB];
            #pragma unroll
            for (int r = 0; r < BB; r++) t_rc1[r] = tanhf(rv[r] + c_brec);

            __syncthreads();   // FULL1: wait h0nxt + ew1_s

            // ---- E: in1 ----
            ull iX[4] = {0,0,0,0}, iY[4] = {0,0,0,0};
            gemm2h<32, NSMC>(sE, j, jx, WE + j, WE + jx,
                             (const ulonglong2*)h0nxt + s * 128, iX, iY);
            float iv[4];
            combineShfl(iX, iY, iv);
            float i1t[BB];
            #pragma unroll
            for (int r = 0; r < BB; r++) i1t[r] = tanhf(iv[r] + c_bin1);

            __syncthreads();   // FULL2: wait skp

            // ---- F: cell1 + LN1 + skip ----
            float4 sk4 = *(const float4*)(skp + j * 4);
            float skv[4] = { sk4.x, sk4.y, sk4.z, sk4.w };
            float ewl[4] = { ew1_s[0], ew1_s[1], ew1_s[2], ew1_s[3] };
            float v1[BB], vf[8];
            #pragma unroll
            for (int r = 0; r < BB; r++) {
                float h = hown[r];
                v1[r] = h + it * (-h + i1t[r] + t_rc1[r]) * (1.f + ewl[r]);
                vf[2 * r]     = v1[r];
                vf[2 * r + 1] = v1[r] * v1[r];
            }
            group_reduce<8>(vf, 2, j, red, stat);
            #pragma unroll
            for (int r = 0; r < BB; r++) {
                float mu  = stat[2 * r] * (1.f / H);
                float var = stat[2 * r + 1] * (1.f / H) - mu * mu;
                hown[r] = (v1[r] - mu) * rsqrtf(var + EPSC) * c_g + c_b + skv[r];
            }
            writePair(h1nxt, j, hown);
            // next step's barx(2) orders these writes
        }
    }

    // ---- Final readout: out[b] = h1 @ Wout + bout (g1) ----
    __syncthreads();
    if (g == 1) {
        float oc[BB];
        #pragma unroll
        for (int r = 0; r < BB; r++) oc[r] = hown[r] * c_wout;
        group_reduce<4>(oc, 2, j, red, stat);
        if (j < BB) out[row0 + j] = stat[j] + bout[0];
    }
}

extern "C" void kernel_launch(void* const* d_in, const int* in_sizes, int n_in,
                              void* d_out, int out_size) {
    const float* x      = (const float*)d_in[0];
    const float* Win0   = (const float*)d_in[1];
    const float* bin0   = (const float*)d_in[2];
    const float* Wrec0  = (const float*)d_in[3];
    const float* brec0  = (const float*)d_in[4];
    const float* Wattn0 = (const float*)d_in[5];
    const float* battn0 = (const float*)d_in[6];
    const float* Wev0   = (const float*)d_in[7];
    const float* bev0   = (const float*)d_in[8];
    const float* tau0   = (const float*)d_in[9];
    const float* gamma0 = (const float*)d_in[10];
    const float* beta0  = (const float*)d_in[11];
    const float* Win1   = (const float*)d_in[12];
    const float* bin1   = (const float*)d_in[13];
    const float* Wrec1  = (const float*)d_in[14];
    const float* brec1  = (const float*)d_in[15];
    const float* Wattn1 = (const float*)d_in[16];
    const float* battn1 = (const float*)d_in[17];
    const float* Wev1   = (const float*)d_in[18];
    const float* bev1   = (const float*)d_in[19];
    const float* tau1   = (const float*)d_in[20];
    const float* gamma1 = (const float*)d_in[21];
    const float* beta1  = (const float*)d_in[22];
    const float* Wskip  = (const float*)d_in[23];
    const float* bskip  = (const float*)d_in[24];
    const float* Wout   = (const float*)d_in[25];
    const float* bout   = (const float*)d_in[26];

    float* out = (float*)d_out;
    float* ew0 = out + BATCH;
    float* ew1 = ew0 + (size_t)BATCH * TT;

    const int TOT = 6 * H * H + INP * H;
    transpose_kernel<<<(TOT + 255) / 256, 256>>>(Wattn0, Wattn1, Wrec0, Wrec1,
                                                 Win1, Wskip, Win0);
    ew0_kernel<<<(BATCH * TT + 255) / 256, 256>>>(x, Wev0, bev0, ew0);

    static int smem_set = 0;
    if (!smem_set) {
        cudaFuncSetAttribute(liquid_kernel,
                             cudaFuncAttributeMaxDynamicSharedMemorySize,
                             SMEM_BYTES);
        smem_set = 1;
    }

    liquid_kernel<<<GRID, NT, SMEM_BYTES>>>(
        x, bin0, brec0, battn0, tau0, gamma0, beta0,
        bin1, brec1, battn1, Wev1, bev1, tau1, gamma1, beta1,
        bskip, Wout, bout,
        out, ew0, ew1);
}